// round 2
// baseline (speedup 1.0000x reference)
#include <cuda_runtime.h>
#include <math.h>

#define BATCH   4
#define SEQ     4096
#define DMODEL  1024
#define HEADS   16
#define DKC     64
#define HALF    512
#define NSEG    8

// ---------------- scratch (device globals; no allocations) ----------------
__device__ float g_cos[SEQ * HALF];                    //  8 MB
__device__ float g_sin[SEQ * HALF];                    //  8 MB
__device__ float g_keyx[BATCH * SEQ * DMODEL];         // 64 MB  xpos(k@wk^T)
__device__ float g_qs[BATCH * DKC * DMODEL];           //  1 MB  xpos(q@wq^T) rows s<64
__device__ float g_kp_part[NSEG * BATCH * DMODEL * DKC];
__device__ float g_T_part [NSEG * BATCH * DKC * DMODEL];
__device__ float g_kp[BATCH * DMODEL * DKC];           // kp[b][d'][e]
__device__ float g_T [BATCH * DKC * DMODEL];           // T[b][e][c]
__device__ float g_vp[BATCH * DMODEL * DKC];           // vp[b][f'][e]
__device__ float g_ysmall[BATCH * DKC * DMODEL];       // y rows s<64
__device__ float g_z[BATCH * DKC * DMODEL];            // groupnormed, s<64
__device__ float g_zbar[BATCH * DMODEL];               // groupnormed, s>=64 (constant in s)
__device__ float g_act[BATCH * SEQ * DMODEL];          // 64 MB  silu(gate)

// ---------------- xpos tables ----------------
__global__ void build_tables() {
    int idx = blockIdx.x * blockDim.x + threadIdx.x;
    if (idx >= SEQ * HALF) return;
    int s = idx / HALF, i = idx % HALF;
    float sv    = (2.0f * i + 0.4f * DMODEL) / (1.4f * DMODEL);
    float scale = powf(sv, (float)s / 512.0f);
    float invf  = powf(10000.0f, -(float)i / (float)HALF);
    float ang   = (float)s * invf;
    g_cos[idx] = cosf(ang) * scale;
    g_sin[idx] = sinf(ang) * scale;
}

// ---------------- generic NT GEMM: C[m,n] = sum_c A[m,c] * W[n,c] ----------------
// EPI: 0 none, 1 xpos, 2 gate(z)*silu.  SMALLM: A-rows gathered as (m/64)*SEQ + m%64.
template<int EPI, bool SMALLM>
__global__ __launch_bounds__(256, 2)
void gemm_kernel(const float* __restrict__ A, const float* __restrict__ W,
                 float* __restrict__ C)
{
    __shared__ float As[16][132];
    __shared__ float Bs[16][132];
    const int tid = threadIdx.x;
    const int m0 = blockIdx.y * 128;
    const int n0 = blockIdx.x * 128;
    const int tx = tid & 15;
    const int ty = tid >> 4;
    const int lr = tid >> 2;          // 0..63
    const int lc = (tid & 3) << 2;    // 0,4,8,12

    int ga0, ga1;
    {
        int ma = m0 + lr, mb = m0 + lr + 64;
        ga0 = SMALLM ? ((ma >> 6) * SEQ + (ma & 63)) : ma;
        ga1 = SMALLM ? ((mb >> 6) * SEQ + (mb & 63)) : mb;
    }
    const float* Ar0 = A + ga0 * DMODEL + lc;
    const float* Ar1 = A + ga1 * DMODEL + lc;
    const float* Br0 = W + (n0 + lr) * DMODEL + lc;
    const float* Br1 = W + (n0 + lr + 64) * DMODEL + lc;

    float acc[8][8];
#pragma unroll
    for (int i = 0; i < 8; ++i)
#pragma unroll
        for (int j = 0; j < 8; ++j) acc[i][j] = 0.f;

    float4 pa0 = *(const float4*)(Ar0);
    float4 pa1 = *(const float4*)(Ar1);
    float4 pb0 = *(const float4*)(Br0);
    float4 pb1 = *(const float4*)(Br1);

    const int KT = DMODEL / 16;
    for (int kt = 0; kt < KT; ++kt) {
        As[lc + 0][lr]      = pa0.x; As[lc + 1][lr]      = pa0.y;
        As[lc + 2][lr]      = pa0.z; As[lc + 3][lr]      = pa0.w;
        As[lc + 0][lr + 64] = pa1.x; As[lc + 1][lr + 64] = pa1.y;
        As[lc + 2][lr + 64] = pa1.z; As[lc + 3][lr + 64] = pa1.w;
        Bs[lc + 0][lr]      = pb0.x; Bs[lc + 1][lr]      = pb0.y;
        Bs[lc + 2][lr]      = pb0.z; Bs[lc + 3][lr]      = pb0.w;
        Bs[lc + 0][lr + 64] = pb1.x; Bs[lc + 1][lr + 64] = pb1.y;
        Bs[lc + 2][lr + 64] = pb1.z; Bs[lc + 3][lr + 64] = pb1.w;
        __syncthreads();
        if (kt < KT - 1) {
            int off = (kt + 1) * 16;
            pa0 = *(const float4*)(Ar0 + off);
            pa1 = *(const float4*)(Ar1 + off);
            pb0 = *(const float4*)(Br0 + off);
            pb1 = *(const float4*)(Br1 + off);
        }
#pragma unroll
        for (int kk = 0; kk < 16; ++kk) {
            float a[8], b[8];
            *(float4*)&a[0] = *(const float4*)&As[kk][ty * 4];
            *(float4*)&a[4] = *(const float4*)&As[kk][ty * 4 + 64];
            *(float4*)&b[0] = *(const float4*)&Bs[kk][tx * 4];
            *(float4*)&b[4] = *(const float4*)&Bs[kk][tx * 4 + 64];
#pragma unroll
            for (int i = 0; i < 8; ++i)
#pragma unroll
                for (int j = 0; j < 8; ++j)
                    acc[i][j] = fmaf(a[i], b[j], acc[i][j]);
        }
        __syncthreads();
    }

    // epilogue
#pragma unroll
    for (int i = 0; i < 8; ++i) {
        int mloc = (i < 4) ? (ty * 4 + i) : (64 + ty * 4 + i - 4);
        int m = m0 + mloc;
        int s, bb;
        if (SMALLM) { s = m & 63;        bb = m >> 6;  }
        else        { s = m & (SEQ - 1); bb = m >> 12; }
#pragma unroll
        for (int jh = 0; jh < 2; ++jh) {
            int nb = n0 + jh * 64 + tx * 4;
            float v0 = acc[i][jh * 4 + 0], v1 = acc[i][jh * 4 + 1];
            float v2 = acc[i][jh * 4 + 2], v3 = acc[i][jh * 4 + 3];
            if (EPI == 1) {
                int p = s * HALF + (nb >> 1);
                float c0 = g_cos[p],     s0 = g_sin[p];
                float c1 = g_cos[p + 1], s1 = g_sin[p + 1];
                float o0 = v0 * c0 - v1 * s0;
                float o1 = v1 * c0 + v0 * s0;
                float o2 = v2 * c1 - v3 * s1;
                float o3 = v3 * c1 + v2 * s1;
                v0 = o0; v1 = o1; v2 = o2; v3 = o3;
            } else if (EPI == 2) {
                const float* zr = (s < DKC) ? (g_z + (bb * DKC + s) * DMODEL)
                                            : (g_zbar + bb * DMODEL);
                float4 z = *(const float4*)(zr + nb);
                v0 *= z.x; v1 *= z.y; v2 *= z.z; v3 *= z.w;
                v0 = v0 / (1.f + expf(-v0));
                v1 = v1 / (1.f + expf(-v1));
                v2 = v2 / (1.f + expf(-v2));
                v3 = v3 / (1.f + expf(-v3));
            }
            float4 o = make_float4(v0, v1, v2, v3);
            *(float4*)(C + m * DMODEL + nb) = o;
        }
    }
}

// ---------------- sequence contraction: OUT[b,i,e] or [b,e,i] = sum_s X[b,s,i]*wx[e,s] ----
// Deterministic: each (seg) writes its own partial block; tree-summed later.
template<bool E_MAJOR>
__global__ __launch_bounds__(256)
void seq_reduce(const float* __restrict__ X, const float* __restrict__ wx,
                float* __restrict__ OUTP)
{
    __shared__ float Xs[64][68];
    __shared__ float Ws[64][68];
    const int i0  = blockIdx.x * 64;
    const int b   = blockIdx.y;
    const int seg = blockIdx.z;
    const int tid = threadIdx.x;
    const int ti = tid & 15, te = tid >> 4;

    float acc[4][4];
#pragma unroll
    for (int a = 0; a < 4; ++a)
#pragma unroll
        for (int j = 0; j < 4; ++j) acc[a][j] = 0.f;

    for (int ch = 0; ch < 8; ++ch) {
        int sb = seg * 512 + ch * 64;
#pragma unroll
        for (int r = 0; r < 16; ++r) {
            int l = r * 256 + tid;
            int row = l >> 6, col = l & 63;
            Xs[row][col] = X[(b * SEQ + sb + row) * DMODEL + i0 + col];
            Ws[row][col] = wx[row * SEQ + sb + col];
        }
        __syncthreads();
        for (int s = 0; s < 64; ++s) {
            float4 xv = *(const float4*)&Xs[s][ti * 4];
            float w0 = Ws[te * 4 + 0][s];
            float w1 = Ws[te * 4 + 1][s];
            float w2 = Ws[te * 4 + 2][s];
            float w3 = Ws[te * 4 + 3][s];
            acc[0][0] += xv.x * w0; acc[0][1] += xv.x * w1; acc[0][2] += xv.x * w2; acc[0][3] += xv.x * w3;
            acc[1][0] += xv.y * w0; acc[1][1] += xv.y * w1; acc[1][2] += xv.y * w2; acc[1][3] += xv.y * w3;
            acc[2][0] += xv.z * w0; acc[2][1] += xv.z * w1; acc[2][2] += xv.z * w2; acc[2][3] += xv.z * w3;
            acc[3][0] += xv.w * w0; acc[3][1] += xv.w * w1; acc[3][2] += xv.w * w2; acc[3][3] += xv.w * w3;
        }
        __syncthreads();
    }
    const int base = seg * (BATCH * DMODEL * DKC);
#pragma unroll
    for (int a = 0; a < 4; ++a)
#pragma unroll
        for (int j = 0; j < 4; ++j) {
            int ii = i0 + ti * 4 + a, e = te * 4 + j;
            int idx = E_MAJOR ? ((b * DKC + e) * DMODEL + ii)
                              : ((b * DMODEL + ii) * DKC + e);
            OUTP[base + idx] = acc[a][j];
        }
}

__global__ void finish_kp(const float* __restrict__ wxb) {
    int idx = blockIdx.x * blockDim.x + threadIdx.x;   // < BATCH*DMODEL*DKC
    float v = 0.f;
#pragma unroll
    for (int s = 0; s < NSEG; ++s) v += g_kp_part[s * (BATCH * DMODEL * DKC) + idx];
    g_kp[idx] = v + wxb[idx & 63];
}
__global__ void finish_T() {
    int idx = blockIdx.x * blockDim.x + threadIdx.x;
    float v = 0.f;
#pragma unroll
    for (int s = 0; s < NSEG; ++s) v += g_T_part[s * (BATCH * DKC * DMODEL) + idx];
    g_T[idx] = v;
}

// ---------------- vp[b,f,e] = sum_c wv[f,c]*T[b,e,c] + wxb[e] ----------------
__global__ __launch_bounds__(256)
void vp_kernel(const float* __restrict__ wv, const float* __restrict__ wxb)
{
    __shared__ float Wvs[64][68];
    __shared__ float Ts[64][68];
    const int f0 = blockIdx.x * 64;
    const int b  = blockIdx.y;
    const int tid = threadIdx.x;
    const int tf = tid & 15, te = tid >> 4;
    float acc[4][4];
#pragma unroll
    for (int a = 0; a < 4; ++a)
#pragma unroll
        for (int j = 0; j < 4; ++j) acc[a][j] = 0.f;

    for (int ch = 0; ch < 16; ++ch) {
        int cb = ch * 64;
#pragma unroll
        for (int r = 0; r < 16; ++r) {
            int l = r * 256 + tid;
            int row = l >> 6, col = l & 63;
            Wvs[row][col] = wv[(f0 + row) * DMODEL + cb + col];
            Ts[row][col]  = g_T[(b * DKC + row) * DMODEL + cb + col];
        }
        __syncthreads();
        for (int c = 0; c < 64; ++c) {
            float wf0 = Wvs[tf * 4 + 0][c], wf1 = Wvs[tf * 4 + 1][c];
            float wf2 = Wvs[tf * 4 + 2][c], wf3 = Wvs[tf * 4 + 3][c];
            float t0 = Ts[te * 4 + 0][c], t1 = Ts[te * 4 + 1][c];
            float t2 = Ts[te * 4 + 2][c], t3 = Ts[te * 4 + 3][c];
            acc[0][0] += wf0 * t0; acc[0][1] += wf0 * t1; acc[0][2] += wf0 * t2; acc[0][3] += wf0 * t3;
            acc[1][0] += wf1 * t0; acc[1][1] += wf1 * t1; acc[1][2] += wf1 * t2; acc[1][3] += wf1 * t3;
            acc[2][0] += wf2 * t0; acc[2][1] += wf2 * t1; acc[2][2] += wf2 * t2; acc[2][3] += wf2 * t3;
            acc[3][0] += wf3 * t0; acc[3][1] += wf3 * t1; acc[3][2] += wf3 * t2; acc[3][3] += wf3 * t3;
        }
        __syncthreads();
    }
#pragma unroll
    for (int a = 0; a < 4; ++a)
#pragma unroll
        for (int j = 0; j < 4; ++j) {
            int f = f0 + tf * 4 + a, e = te * 4 + j;
            g_vp[(b * DMODEL + f) * DKC + e] = acc[a][j] + wxb[e];
        }
}

// ---------------- tiny attention: only rows s < 64 have non-trivial softmax ----------------
__global__ __launch_bounds__(64)
void attn_small()
{
    __shared__ float kps[64][64];   // [d][e]
    __shared__ float vps[64][64];   // [f][e]
    const int h = blockIdx.x, b = blockIdx.y, s = threadIdx.x;
    for (int l = s; l < 4096; l += 64) {
        int d = l >> 6, e = l & 63;
        kps[d][e] = g_kp[(b * DMODEL + h * DKC + d) * DKC + e];
        vps[d][e] = g_vp[(b * DMODEL + h * DKC + d) * DKC + e];
    }
    __syncthreads();

    float qv[64];
    const float* qp = g_qs + (b * DKC + s) * DMODEL + h * DKC;
#pragma unroll
    for (int d = 0; d < 64; d += 4) {
        float4 t = *(const float4*)(qp + d);
        qv[d] = t.x; qv[d + 1] = t.y; qv[d + 2] = t.z; qv[d + 3] = t.w;
    }
    const float lg0 = logf(1.0f / 32.0f);
    const float lg1 = logf(1.0f / 512.0f);
    const float gamma = 1.0f - expf(lg0 + (lg1 - lg0) * ((float)h / 15.0f));

    float sc[64];
#pragma unroll
    for (int e = 0; e < 64; ++e) {
        float a = 0.f;
#pragma unroll
        for (int d = 0; d < 64; ++d) a = fmaf(qv[d], kps[d][e], a);
        float dt = (e >= s) ? powf(gamma, (float)(e - s)) : 0.0f;
        sc[e] = a * dt;
    }
    float mx = -1e30f;
#pragma unroll
    for (int e = 0; e < 64; ++e) mx = fmaxf(mx, sc[e]);
    float sum = 0.f;
#pragma unroll
    for (int e = 0; e < 64; ++e) { sc[e] = expf(sc[e] - mx); sum += sc[e]; }
    float inv = 1.0f / sum;
#pragma unroll
    for (int f = 0; f < 64; ++f) {
        float a = 0.f;
#pragma unroll
        for (int e = 0; e < 64; ++e) a = fmaf(sc[e], vps[f][e], a);
        g_ysmall[(b * DKC + s) * DMODEL + h * DKC + f] = a * inv;
    }
}

// ---------------- group norm helpers (groups of 4 contiguous dims, w/b indexed d%64) ----
__device__ __forceinline__ void gn4(float y[4], int d0,
                                    const float* gw, const float* gb, float out[4]) {
    float mu = (y[0] + y[1] + y[2] + y[3]) * 0.25f;
    float var = 0.f;
#pragma unroll
    for (int j = 0; j < 4; ++j) { float dd = y[j] - mu; var += dd * dd; }
    var *= 0.25f;
    float inv = rsqrtf(var + 1e-5f);
#pragma unroll
    for (int j = 0; j < 4; ++j) {
        int d = d0 + j;
        out[j] = (y[j] - mu) * inv * gw[d & 63] + gb[d & 63];
    }
}

__global__ void zbar_kernel(const float* __restrict__ gw, const float* __restrict__ gb) {
    int b = blockIdx.x, t = threadIdx.x;   // 256 threads: one 4-group each
    int d0 = t * 4;
    float y[4];
#pragma unroll
    for (int j = 0; j < 4; ++j) {
        const float* vp = g_vp + (b * DMODEL + d0 + j) * DKC;
        float s = 0.f;
#pragma unroll
        for (int e = 0; e < 64; ++e) s += vp[e];
        y[j] = s * (1.0f / 64.0f);
    }
    float o[4];
    gn4(y, d0, gw, gb, o);
#pragma unroll
    for (int j = 0; j < 4; ++j) g_zbar[b * DMODEL + d0 + j] = o[j];
}

__global__ void gn_small(const float* __restrict__ gw, const float* __restrict__ gb) {
    int row = blockIdx.x;                  // b*64 + s, 256 rows
    int d0 = threadIdx.x * 4;
    float4 y4 = *(const float4*)(g_ysmall + row * DMODEL + d0);
    float y[4] = { y4.x, y4.y, y4.z, y4.w };
    float o[4];
    gn4(y, d0, gw, gb, o);
    float4 o4 = make_float4(o[0], o[1], o[2], o[3]);
    *(float4*)(g_z + row * DMODEL + d0) = o4;
}

// ---------------- launch ----------------
extern "C" void kernel_launch(void* const* d_in, const int* in_sizes, int n_in,
                              void* d_out, int out_size)
{
    const float* q   = (const float*)d_in[0];
    const float* k   = (const float*)d_in[1];
    const float* v   = (const float*)d_in[2];
    const float* wq  = (const float*)d_in[3];
    const float* wk  = (const float*)d_in[4];
    const float* wv  = (const float*)d_in[5];
    const float* wo  = (const float*)d_in[6];
    const float* wg  = (const float*)d_in[7];
    const float* wxw = (const float*)d_in[8];
    const float* wxb = (const float*)d_in[9];
    const float* gnw = (const float*)d_in[10];
    const float* gnb = (const float*)d_in[11];
    float* out = (float*)d_out;

    float *p_keyx, *p_qs, *p_act, *p_kpp, *p_tp;
    cudaGetSymbolAddress((void**)&p_keyx, g_keyx);
    cudaGetSymbolAddress((void**)&p_qs,   g_qs);
    cudaGetSymbolAddress((void**)&p_act,  g_act);
    cudaGetSymbolAddress((void**)&p_kpp,  g_kp_part);
    cudaGetSymbolAddress((void**)&p_tp,   g_T_part);

    build_tables<<<(SEQ * HALF + 255) / 256, 256>>>();

    // keyx = xpos(k @ wk^T)  [full], qs = xpos(q @ wq^T) [rows s<64 only]
    gemm_kernel<1, false><<<dim3(8, 128), 256>>>(k, wk, p_keyx);
    gemm_kernel<1, true ><<<dim3(8, 2),   256>>>(q, wq, p_qs);

    // kp[b,d',e] = sum_s keyx * wx ;  T[b,e,c] = sum_s wx * v
    seq_reduce<false><<<dim3(16, BATCH, NSEG), 256>>>(p_keyx, wxw, p_kpp);
    seq_reduce<true ><<<dim3(16, BATCH, NSEG), 256>>>(v,      wxw, p_tp);
    finish_kp<<<(BATCH * DMODEL * DKC) / 256, 256>>>(wxb);
    finish_T <<<(BATCH * DKC * DMODEL) / 256, 256>>>();

    // vp[b,f,e] = wv @ T + wxb
    vp_kernel<<<dim3(16, BATCH), 256>>>(wv, wxb);

    // softmax attention (only s<64 rows are non-uniform)
    attn_small<<<dim3(HEADS, BATCH), 64>>>();

    // group norm: constant rows (s>=64) and small rows (s<64)
    zbar_kernel<<<BATCH, 256>>>(gnw, gnb);
    gn_small<<<BATCH * DKC, 256>>>(gnw, gnb);

    // act = silu((q @ wg^T) * z) ; out = act @ wo^T
    gemm_kernel<2, false><<<dim3(8, 128), 256>>>(q, wg, p_act);
    gemm_kernel<0, false><<<dim3(8, 128), 256>>>(p_act, wo, out);
}

// round 5
// speedup vs baseline: 1.6522x; 1.6522x over previous
#include <cuda_runtime.h>
#include <cuda_bf16.h>
#include <math.h>
#include <stdint.h>

#define BATCH   4
#define SEQ     4096
#define DMODEL  1024
#define HEADS   16
#define DKC     64
#define HALF    512
#define NSEG    8
#define MTOT    (BATCH * SEQ)    /* 16384 */

// ---------------- scratch (device globals; no allocations) ----------------
__device__ float g_cos[SEQ * HALF];
__device__ float g_sin[SEQ * HALF];
__device__ float g_keyx[MTOT * DMODEL];                 // xpos(k@wk^T) fp32
__device__ float g_qs[BATCH * DKC * DMODEL];            // xpos(q@wq^T) rows s<64
__device__ float g_kp_part[NSEG * BATCH * DMODEL * DKC];
__device__ float g_T_part [NSEG * BATCH * DKC * DMODEL];
__device__ float g_kp[BATCH * DMODEL * DKC];
__device__ float g_T [BATCH * DKC * DMODEL];
__device__ float g_vp[BATCH * DMODEL * DKC];
__device__ float g_ysmall[BATCH * DKC * DMODEL];
__device__ float g_z[BATCH * DKC * DMODEL];
__device__ float g_zbar[BATCH * DMODEL];

// bf16 split operands
__device__ __nv_bfloat16 g_qhi[MTOT * DMODEL], g_qlo[MTOT * DMODEL];
__device__ __nv_bfloat16 g_khi[MTOT * DMODEL], g_klo[MTOT * DMODEL];
__device__ __nv_bfloat16 g_ahi[MTOT * DMODEL], g_alo[MTOT * DMODEL];   // silu(gate)
__device__ __nv_bfloat16 g_wkhi[DMODEL * DMODEL], g_wklo[DMODEL * DMODEL];
__device__ __nv_bfloat16 g_wghi[DMODEL * DMODEL], g_wglo[DMODEL * DMODEL];
__device__ __nv_bfloat16 g_wohi[DMODEL * DMODEL], g_wolo[DMODEL * DMODEL];

// ================= small PTX helpers (all plain-sm_103-legal) =================
__device__ __forceinline__ uint32_t smem_u32(const void* p) {
    uint32_t a;
    asm("{ .reg .u64 t; cvta.to.shared.u64 t, %1; cvt.u32.u64 %0, t; }" : "=r"(a) : "l"(p));
    return a;
}
__device__ __forceinline__ void cp16(uint32_t dst, const void* src) {
    asm volatile("cp.async.cg.shared.global [%0], [%1], 16;" :: "r"(dst), "l"(src) : "memory");
}
#define CP_COMMIT() asm volatile("cp.async.commit_group;" ::: "memory")
#define CP_WAIT(N)  asm volatile("cp.async.wait_group %0;" :: "n"(N) : "memory")

__device__ __forceinline__ void ldsm4(uint32_t* r, uint32_t addr) {
    asm volatile("ldmatrix.sync.aligned.m8n8.x4.shared.b16 {%0,%1,%2,%3}, [%4];"
                 : "=r"(r[0]), "=r"(r[1]), "=r"(r[2]), "=r"(r[3]) : "r"(addr));
}
__device__ __forceinline__ void mma16816(float* d, const uint32_t* a, const uint32_t* b) {
    asm volatile("mma.sync.aligned.m16n8k16.row.col.f32.bf16.bf16.f32 "
                 "{%0,%1,%2,%3}, {%4,%5,%6,%7}, {%8,%9}, {%0,%1,%2,%3};"
                 : "+f"(d[0]), "+f"(d[1]), "+f"(d[2]), "+f"(d[3])
                 : "r"(a[0]), "r"(a[1]), "r"(a[2]), "r"(a[3]), "r"(b[0]), "r"(b[1]));
}

// SMEM stage layout (bytes): rows padded to 80B (40 bf16) for conflict-free ldmatrix
#define ROWB      80
#define STG_BYTES 40960
#define A_LO_OFF  10240
#define B_HI_OFF  20480
#define B_LO_OFF  30720
#define SMEM_HMMA (2 * STG_BYTES)   /* 81920 */

// ================= xpos tables =================
__global__ void build_tables() {
    int idx = blockIdx.x * blockDim.x + threadIdx.x;
    if (idx >= SEQ * HALF) return;
    int s = idx / HALF, i = idx % HALF;
    float sv    = (2.0f * i + 0.4f * DMODEL) / (1.4f * DMODEL);
    float scale = powf(sv, (float)s / 512.0f);
    float invf  = powf(10000.0f, -(float)i / (float)HALF);
    float ang   = (float)s * invf;
    g_cos[idx] = cosf(ang) * scale;
    g_sin[idx] = sinf(ang) * scale;
}

// ================= fp32 -> (hi, lo) bf16 split =================
__global__ void split_bf16(const float* __restrict__ x, __nv_bfloat16* __restrict__ hi,
                           __nv_bfloat16* __restrict__ lo, int n4) {
    int i = blockIdx.x * blockDim.x + threadIdx.x;
    if (i >= n4) return;
    float4 v = ((const float4*)x)[i];
    __nv_bfloat16 h0 = __float2bfloat16(v.x), h1 = __float2bfloat16(v.y);
    __nv_bfloat16 h2 = __float2bfloat16(v.z), h3 = __float2bfloat16(v.w);
    __nv_bfloat16 l0 = __float2bfloat16(v.x - __bfloat162float(h0));
    __nv_bfloat16 l1 = __float2bfloat16(v.y - __bfloat162float(h1));
    __nv_bfloat16 l2 = __float2bfloat16(v.z - __bfloat162float(h2));
    __nv_bfloat16 l3 = __float2bfloat16(v.w - __bfloat162float(h3));
    __nv_bfloat162* ph = (__nv_bfloat162*)(hi) + i * 2;
    __nv_bfloat162* pl = (__nv_bfloat162*)(lo) + i * 2;
    ph[0] = __halves2bfloat162(h0, h1); ph[1] = __halves2bfloat162(h2, h3);
    pl[0] = __halves2bfloat162(l0, l1); pl[1] = __halves2bfloat162(l2, l3);
}

// ================= HMMA split GEMM: C[m,n] = sum_k A[m,k]*W[n,k] =================
// CTA tile 128x128, warp tile 64x32 (2x4 warps), K in 32 chunks of 32, 2-stage pipeline.
// Three passes per k16: Ahi*Bhi + Alo*Bhi + Ahi*Blo (fp32 accum in registers).
__device__ __forceinline__ void hmma_load_stage(
    uint32_t sb, int stage, int kc, int m0, int n0, int tid,
    const __nv_bfloat16* __restrict__ Ahi, const __nv_bfloat16* __restrict__ Alo,
    const __nv_bfloat16* __restrict__ Whi, const __nv_bfloat16* __restrict__ Wlo)
{
    const uint32_t base = sb + (uint32_t)stage * STG_BYTES;
    const int koff = kc * 32;
#pragma unroll
    for (int p = 0; p < 2; ++p) {
        int i = p * 256 + tid;
        int r = i >> 2, u = i & 3;
        size_t gofA = (size_t)(m0 + r) * DMODEL + koff + u * 8;
        size_t gofB = (size_t)(n0 + r) * DMODEL + koff + u * 8;
        uint32_t soff = (uint32_t)(r * ROWB + u * 16);
        cp16(base + soff,            Ahi + gofA);
        cp16(base + A_LO_OFF + soff, Alo + gofA);
        cp16(base + B_HI_OFF + soff, Whi + gofB);
        cp16(base + B_LO_OFF + soff, Wlo + gofB);
    }
    CP_COMMIT();
}

template<int EPI>
__global__ __launch_bounds__(256)
void hmma_gemm(const __nv_bfloat16* __restrict__ Ahi, const __nv_bfloat16* __restrict__ Alo,
               const __nv_bfloat16* __restrict__ Whi, const __nv_bfloat16* __restrict__ Wlo,
               float* __restrict__ Cf,
               __nv_bfloat16* __restrict__ Chi, __nv_bfloat16* __restrict__ Clo)
{
    extern __shared__ char smem[];
    const uint32_t sb = smem_u32(smem);
    const int tid = threadIdx.x, wid = tid >> 5, lane = tid & 31;
    const int warp_m = wid >> 2, warp_n = wid & 3;
    const int n0 = blockIdx.x * 128, m0 = blockIdx.y * 128;

    float acc[4][4][4];
#pragma unroll
    for (int i = 0; i < 4; ++i)
#pragma unroll
        for (int j = 0; j < 4; ++j)
#pragma unroll
            for (int c = 0; c < 4; ++c) acc[i][j][c] = 0.f;

    // lane-dependent ldmatrix byte offsets
    uint32_t aoff[4], boff[2];
#pragma unroll
    for (int atom = 0; atom < 4; ++atom)
        aoff[atom] = (uint32_t)((warp_m * 64 + atom * 16 + (lane & 15)) * ROWB
                                + ((lane >> 4) & 1) * 16);
#pragma unroll
    for (int p = 0; p < 2; ++p)
        boff[p] = (uint32_t)((warp_n * 32 + p * 16 + (lane & 7) + ((lane >> 4) << 3)) * ROWB
                             + ((lane >> 3) & 1) * 16);

    hmma_load_stage(sb, 0, 0, m0, n0, tid, Ahi, Alo, Whi, Wlo);
    hmma_load_stage(sb, 1, 1, m0, n0, tid, Ahi, Alo, Whi, Wlo);

    for (int kc = 0; kc < 32; ++kc) {
        if (kc >= 30) { CP_WAIT(0); } else { CP_WAIT(1); }
        __syncthreads();
        const uint32_t stgb = sb + (uint32_t)(kc & 1) * STG_BYTES;
#pragma unroll
        for (int ks = 0; ks < 2; ++ks) {
            const uint32_t kb = (uint32_t)(ks * 32);
            uint32_t ahi[4][4], alo[4][4], bhi[2][4], blo[2][4];
#pragma unroll
            for (int atom = 0; atom < 4; ++atom) {
                ldsm4(ahi[atom], stgb + aoff[atom] + kb);
                ldsm4(alo[atom], stgb + A_LO_OFF + aoff[atom] + kb);
            }
#pragma unroll
            for (int p = 0; p < 2; ++p) {
                ldsm4(bhi[p], stgb + B_HI_OFF + boff[p] + kb);
                ldsm4(blo[p], stgb + B_LO_OFF + boff[p] + kb);
            }
#pragma unroll
            for (int im = 0; im < 4; ++im)
#pragma unroll
                for (int in = 0; in < 4; ++in)
                    mma16816(acc[im][in], ahi[im], &bhi[in >> 1][(in & 1) * 2]);
#pragma unroll
            for (int im = 0; im < 4; ++im)
#pragma unroll
                for (int in = 0; in < 4; ++in)
                    mma16816(acc[im][in], alo[im], &bhi[in >> 1][(in & 1) * 2]);
#pragma unroll
            for (int im = 0; im < 4; ++im)
#pragma unroll
                for (int in = 0; in < 4; ++in)
                    mma16816(acc[im][in], ahi[im], &blo[in >> 1][(in & 1) * 2]);
        }
        __syncthreads();
        if (kc + 2 < 32)
            hmma_load_stage(sb, kc & 1, kc + 2, m0, n0, tid, Ahi, Alo, Whi, Wlo);
    }

    // -------- epilogue --------
#pragma unroll
    for (int im = 0; im < 4; ++im) {
#pragma unroll
        for (int in = 0; in < 4; ++in) {
            const int nc = n0 + warp_n * 32 + in * 8 + (lane & 3) * 2;
#pragma unroll
            for (int half = 0; half < 2; ++half) {
                const int m = m0 + warp_m * 64 + im * 16 + (lane >> 2) + half * 8;
                const int s = m & (SEQ - 1);
                const int bb = m >> 12;
                float v0 = acc[im][in][half * 2 + 0];
                float v1 = acc[im][in][half * 2 + 1];
                if (EPI == 0) {
                    *(float2*)(Cf + (size_t)m * DMODEL + nc) = make_float2(v0, v1);
                } else if (EPI == 1) {
                    int p = s * HALF + (nc >> 1);
                    float cs = g_cos[p], sn = g_sin[p];
                    float o0 = v0 * cs - v1 * sn;
                    float o1 = v1 * cs + v0 * sn;
                    *(float2*)(Cf + (size_t)m * DMODEL + nc) = make_float2(o0, o1);
                } else {
                    const float* zr = (s < DKC) ? (g_z + (bb * DKC + s) * DMODEL)
                                                : (g_zbar + bb * DMODEL);
                    float a0 = v0 * zr[nc];
                    float a1 = v1 * zr[nc + 1];
                    a0 = a0 / (1.f + expf(-a0));
                    a1 = a1 / (1.f + expf(-a1));
                    __nv_bfloat16 h0 = __float2bfloat16(a0), h1 = __float2bfloat16(a1);
                    __nv_bfloat16 l0 = __float2bfloat16(a0 - __bfloat162float(h0));
                    __nv_bfloat16 l1 = __float2bfloat16(a1 - __bfloat162float(h1));
                    *(__nv_bfloat162*)(Chi + (size_t)m * DMODEL + nc) = __halves2bfloat162(h0, h1);
                    *(__nv_bfloat162*)(Clo + (size_t)m * DMODEL + nc) = __halves2bfloat162(l0, l1);
                }
            }
        }
    }
}

// ================= fp32 SIMT GEMM (tiny wq GEMM only) =================
template<int EPI, bool SMALLM>
__global__ __launch_bounds__(256, 2)
void gemm_kernel(const float* __restrict__ A, const float* __restrict__ W,
                 float* __restrict__ C)
{
    __shared__ float As[16][132];
    __shared__ float Bs[16][132];
    const int tid = threadIdx.x;
    const int m0 = blockIdx.y * 128;
    const int n0 = blockIdx.x * 128;
    const int tx = tid & 15;
    const int ty = tid >> 4;
    const int lr = tid >> 2;
    const int lc = (tid & 3) << 2;

    int ga0, ga1;
    {
        int ma = m0 + lr, mb = m0 + lr + 64;
        ga0 = SMALLM ? ((ma >> 6) * SEQ + (ma & 63)) : ma;
        ga1 = SMALLM ? ((mb >> 6) * SEQ + (mb & 63)) : mb;
    }
    const float* Ar0 = A + ga0 * DMODEL + lc;
    const float* Ar1 = A + ga1 * DMODEL + lc;
    const float* Br0 = W + (n0 + lr) * DMODEL + lc;
    const float* Br1 = W + (n0 + lr + 64) * DMODEL + lc;

    float acc[8][8];
#pragma unroll
    for (int i = 0; i < 8; ++i)
#pragma unroll
        for (int j = 0; j < 8; ++j) acc[i][j] = 0.f;

    float4 pa0 = *(const float4*)(Ar0);
    float4 pa1 = *(const float4*)(Ar1);
    float4 pb0 = *(const float4*)(Br0);
    float4 pb1 = *(const float4*)(Br1);

    const int KT = DMODEL / 16;
    for (int kt = 0; kt < KT; ++kt) {
        As[lc + 0][lr]      = pa0.x; As[lc + 1][lr]      = pa0.y;
        As[lc + 2][lr]      = pa0.z; As[lc + 3][lr]      = pa0.w;
        As[lc + 0][lr + 64] = pa1.x; As[lc + 1][lr + 64] = pa1.y;
        As[lc + 2][lr + 64] = pa1.z; As[lc + 3][lr + 64] = pa1.w;
        Bs[lc + 0][lr]      = pb0.x; Bs[lc + 1][lr]      = pb0.y;
        Bs[lc + 2][lr]      = pb0.z; Bs[lc + 3][lr]      = pb0.w;
        Bs[lc + 0][lr + 64] = pb1.x; Bs[lc + 1][lr + 64] = pb1.y;
        Bs[lc + 2][lr + 64] = pb1.z; Bs[lc + 3][lr + 64] = pb1.w;
        __syncthreads();
        if (kt < KT - 1) {
            int off = (kt + 1) * 16;
            pa0 = *(const float4*)(Ar0 + off);
            pa1 = *(const float4*)(Ar1 + off);
            pb0 = *(const float4*)(Br0 + off);
            pb1 = *(const float4*)(Br1 + off);
        }
#pragma unroll
        for (int kk = 0; kk < 16; ++kk) {
            float a[8], b[8];
            *(float4*)&a[0] = *(const float4*)&As[kk][ty * 4];
            *(float4*)&a[4] = *(const float4*)&As[kk][ty * 4 + 64];
            *(float4*)&b[0] = *(const float4*)&Bs[kk][tx * 4];
            *(float4*)&b[4] = *(const float4*)&Bs[kk][tx * 4 + 64];
#pragma unroll
            for (int i = 0; i < 8; ++i)
#pragma unroll
                for (int j = 0; j < 8; ++j)
                    acc[i][j] = fmaf(a[i], b[j], acc[i][j]);
        }
        __syncthreads();
    }

#pragma unroll
    for (int i = 0; i < 8; ++i) {
        int mloc = (i < 4) ? (ty * 4 + i) : (64 + ty * 4 + i - 4);
        int m = m0 + mloc;
        int s, bb;
        if (SMALLM) { s = m & 63;        bb = m >> 6;  }
        else        { s = m & (SEQ - 1); bb = m >> 12; }
#pragma unroll
        for (int jh = 0; jh < 2; ++jh) {
            int nb = n0 + jh * 64 + tx * 4;
            float v0 = acc[i][jh * 4 + 0], v1 = acc[i][jh * 4 + 1];
            float v2 = acc[i][jh * 4 + 2], v3 = acc[i][jh * 4 + 3];
            if (EPI == 1) {
                int p = s * HALF + (nb >> 1);
                float c0 = g_cos[p],     s0 = g_sin[p];
                float c1 = g_cos[p + 1], s1 = g_sin[p + 1];
                float o0 = v0 * c0 - v1 * s0;
                float o1 = v1 * c0 + v0 * s0;
                float o2 = v2 * c1 - v3 * s1;
                float o3 = v3 * c1 + v2 * s1;
                v0 = o0; v1 = o1; v2 = o2; v3 = o3;
            } else if (EPI == 2) {
                const float* zr = (s < DKC) ? (g_z + (bb * DKC + s) * DMODEL)
                                            : (g_zbar + bb * DMODEL);
                float4 z = *(const float4*)(zr + nb);
                v0 *= z.x; v1 *= z.y; v2 *= z.z; v3 *= z.w;
                v0 = v0 / (1.f + expf(-v0));
                v1 = v1 / (1.f + expf(-v1));
                v2 = v2 / (1.f + expf(-v2));
                v3 = v3 / (1.f + expf(-v3));
            }
            *(float4*)(C + m * DMODEL + nb) = make_float4(v0, v1, v2, v3);
        }
    }
}

// ================= sequence contraction =================
template<bool E_MAJOR>
__global__ __launch_bounds__(256)
void seq_reduce(const float* __restrict__ X, const float* __restrict__ wx,
                float* __restrict__ OUTP)
{
    __shared__ float Xs[64][68];
    __shared__ float Ws[64][68];
    const int i0  = blockIdx.x * 64;
    const int b   = blockIdx.y;
    const int seg = blockIdx.z;
    const int tid = threadIdx.x;
    const int ti = tid & 15, te = tid >> 4;

    float acc[4][4];
#pragma unroll
    for (int a = 0; a < 4; ++a)
#pragma unroll
        for (int j = 0; j < 4; ++j) acc[a][j] = 0.f;

    for (int ch = 0; ch < 8; ++ch) {
        int sb = seg * 512 + ch * 64;
#pragma unroll
        for (int r = 0; r < 16; ++r) {
            int l = r * 256 + tid;
            int row = l >> 6, col = l & 63;
            Xs[row][col] = X[(b * SEQ + sb + row) * DMODEL + i0 + col];
            Ws[row][col] = wx[row * SEQ + sb + col];
        }
        __syncthreads();
        for (int s = 0; s < 64; ++s) {
            float4 xv = *(const float4*)&Xs[s][ti * 4];
            float w0 = Ws[te * 4 + 0][s];
            float w1 = Ws[te * 4 + 1][s];
            float w2 = Ws[te * 4 + 2][s];
            float w3 = Ws[te * 4 + 3][s];
            acc[0][0] += xv.x * w0; acc[0][1] += xv.x * w1; acc[0][2] += xv.x * w2; acc[0][3] += xv.x * w3;
            acc[1][0] += xv.y * w0; acc[1][1] += xv.y * w1; acc[1][2] += xv.y * w2; acc[1][3] += xv.y * w3;
            acc[2][0] += xv.z * w0; acc[2][1] += xv.z * w1; acc[2][2] += xv.z * w2; acc[2][3] += xv.z * w3;
            acc[3][0] += xv.w * w0; acc[3][1] += xv.w * w1; acc[3][2] += xv.w * w2; acc[3][3] += xv.w * w3;
        }
        __syncthreads();
    }
    const int base = seg * (BATCH * DMODEL * DKC);
#pragma unroll
    for (int a = 0; a < 4; ++a)
#pragma unroll
        for (int j = 0; j < 4; ++j) {
            int ii = i0 + ti * 4 + a, e = te * 4 + j;
            int idx = E_MAJOR ? ((b * DKC + e) * DMODEL + ii)
                              : ((b * DMODEL + ii) * DKC + e);
            OUTP[base + idx] = acc[a][j];
        }
}

__global__ void finish_kp(const float* __restrict__ wxb) {
    int idx = blockIdx.x * blockDim.x + threadIdx.x;
    float v = 0.f;
#pragma unroll
    for (int s = 0; s < NSEG; ++s) v += g_kp_part[s * (BATCH * DMODEL * DKC) + idx];
    g_kp[idx] = v + wxb[idx & 63];
}
__global__ void finish_T() {
    int idx = blockIdx.x * blockDim.x + threadIdx.x;
    float v = 0.f;
#pragma unroll
    for (int s = 0; s < NSEG; ++s) v += g_T_part[s * (BATCH * DKC * DMODEL) + idx];
    g_T[idx] = v;
}

// ================= vp =================
__global__ __launch_bounds__(256)
void vp_kernel(const float* __restrict__ wv, const float* __restrict__ wxb)
{
    __shared__ float Wvs[64][68];
    __shared__ float Ts[64][68];
    const int f0 = blockIdx.x * 64;
    const int b  = blockIdx.y;
    const int tid = threadIdx.x;
    const int tf = tid & 15, te = tid >> 4;
    float acc[4][4];
#pragma unroll
    for (int a = 0; a < 4; ++a)
#pragma unroll
        for (int j = 0; j < 4; ++j) acc[a][j] = 0.f;

    for (int ch = 0; ch < 16; ++ch) {
        int cb = ch * 64;
#pragma unroll
        for (int r = 0; r < 16; ++r) {
            int l = r * 256 + tid;
            int row = l >> 6, col = l & 63;
            Wvs[row][col] = wv[(f0 + row) * DMODEL + cb + col];
            Ts[row][col]  = g_T[(b * DKC + row) * DMODEL + cb + col];
        }
        __syncthreads();
        for (int c = 0; c < 64; ++c) {
            float wf0 = Wvs[tf * 4 + 0][c], wf1 = Wvs[tf * 4 + 1][c];
            float wf2 = Wvs[tf * 4 + 2][c], wf3 = Wvs[tf * 4 + 3][c];
            float t0 = Ts[te * 4 + 0][c], t1 = Ts[te * 4 + 1][c];
            float t2 = Ts[te * 4 + 2][c], t3 = Ts[te * 4 + 3][c];
            acc[0][0] += wf0 * t0; acc[0][1] += wf0 * t1; acc[0][2] += wf0 * t2; acc[0][3] += wf0 * t3;
            acc[1][0] += wf1 * t0; acc[1][1] += wf1 * t1; acc[1][2] += wf1 * t2; acc[1][3] += wf1 * t3;
            acc[2][0] += wf2 * t0; acc[2][1] += wf2 * t1; acc[2][2] += wf2 * t2; acc[2][3] += wf2 * t3;
            acc[3][0] += wf3 * t0; acc[3][1] += wf3 * t1; acc[3][2] += wf3 * t2; acc[3][3] += wf3 * t3;
        }
        __syncthreads();
    }
#pragma unroll
    for (int a = 0; a < 4; ++a)
#pragma unroll
        for (int j = 0; j < 4; ++j) {
            int f = f0 + tf * 4 + a, e = te * 4 + j;
            g_vp[(b * DMODEL + f) * DKC + e] = acc[a][j] + wxb[e];
        }
}

// ================= tiny attention =================
__global__ __launch_bounds__(64)
void attn_small()
{
    __shared__ float kps[64][64];
    __shared__ float vps[64][64];
    const int h = blockIdx.x, b = blockIdx.y, s = threadIdx.x;
    for (int l = s; l < 4096; l += 64) {
        int d = l >> 6, e = l & 63;
        kps[d][e] = g_kp[(b * DMODEL + h * DKC + d) * DKC + e];
        vps[d][e] = g_vp[(b * DMODEL + h * DKC + d) * DKC + e];
    }
    __syncthreads();

    float qv[64];
    const float* qp = g_qs + (b * DKC + s) * DMODEL + h * DKC;
#pragma unroll
    for (int d = 0; d < 64; d += 4) {
        float4 t = *(const float4*)(qp + d);
        qv[d] = t.x; qv[d + 1] = t.y; qv[d + 2] = t.z; qv[d + 3] = t.w;
    }
    const float lg0 = logf(1.0f / 32.0f);
    const float lg1 = logf(1.0f / 512.0f);
    const float gamma = 1.0f - expf(lg0 + (lg1 - lg0) * ((float)h / 15.0f));

    float sc[64];
#pragma unroll
    for (int e = 0; e < 64; ++e) {
        float a = 0.f;
#pragma unroll
        for (int d = 0; d < 64; ++d) a = fmaf(qv[d], kps[d][e], a);
        float dt = (e >= s) ? powf(gamma, (float)(e - s)) : 0.0f;
        sc[e] = a * dt;
    }
    float mx = -1e30f;
#pragma unroll
    for (int e = 0; e < 64; ++e) mx = fmaxf(mx, sc[e]);
    float sum = 0.f;
#pragma unroll
    for (int e = 0; e < 64; ++e) { sc[e] = expf(sc[e] - mx); sum += sc[e]; }
    float inv = 1.0f / sum;
#pragma unroll
    for (int f = 0; f < 64; ++f) {
        float a = 0.f;
#pragma unroll
        for (int e = 0; e < 64; ++e) a = fmaf(sc[e], vps[f][e], a);
        g_ysmall[(b * DKC + s) * DMODEL + h * DKC + f] = a * inv;
    }
}

// ================= group norm =================
__device__ __forceinline__ void gn4(float y[4], int d0,
                                    const float* gw, const float* gb, float out[4]) {
    float mu = (y[0] + y[1] + y[2] + y[3]) * 0.25f;
    float var = 0.f;
#pragma unroll
    for (int j = 0; j < 4; ++j) { float dd = y[j] - mu; var += dd * dd; }
    var *= 0.25f;
    float inv = rsqrtf(var + 1e-5f);
#pragma unroll
    for (int j = 0; j < 4; ++j) {
        int d = d0 + j;
        out[j] = (y[j] - mu) * inv * gw[d & 63] + gb[d & 63];
    }
}

__global__ void zbar_kernel(const float* __restrict__ gw, const float* __restrict__ gb) {
    int b = blockIdx.x, t = threadIdx.x;
    int d0 = t * 4;
    float y[4];
#pragma unroll
    for (int j = 0; j < 4; ++j) {
        const float* vp = g_vp + (b * DMODEL + d0 + j) * DKC;
        float s = 0.f;
#pragma unroll
        for (int e = 0; e < 64; ++e) s += vp[e];
        y[j] = s * (1.0f / 64.0f);
    }
    float o[4];
    gn4(y, d0, gw, gb, o);
#pragma unroll
    for (int j = 0; j < 4; ++j) g_zbar[b * DMODEL + d0 + j] = o[j];
}

__global__ void gn_small(const float* __restrict__ gw, const float* __restrict__ gb) {
    int row = blockIdx.x;
    int d0 = threadIdx.x * 4;
    float4 y4 = *(const float4*)(g_ysmall + row * DMODEL + d0);
    float y[4] = { y4.x, y4.y, y4.z, y4.w };
    float o[4];
    gn4(y, d0, gw, gb, o);
    *(float4*)(g_z + row * DMODEL + d0) = make_float4(o[0], o[1], o[2], o[3]);
}

// ================= launch =================
extern "C" void kernel_launch(void* const* d_in, const int* in_sizes, int n_in,
                              void* d_out, int out_size)
{
    const float* q   = (const float*)d_in[0];
    const float* k   = (const float*)d_in[1];
    const float* v   = (const float*)d_in[2];
    const float* wq  = (const float*)d_in[3];
    const float* wk  = (const float*)d_in[4];
    const float* wv  = (const float*)d_in[5];
    const float* wo  = (const float*)d_in[6];
    const float* wg  = (const float*)d_in[7];
    const float* wxw = (const float*)d_in[8];
    const float* wxb = (const float*)d_in[9];
    const float* gnw = (const float*)d_in[10];
    const float* gnb = (const float*)d_in[11];
    float* out = (float*)d_out;

    float *p_keyx, *p_qs, *p_kpp, *p_tp;
    cudaGetSymbolAddress((void**)&p_keyx, g_keyx);
    cudaGetSymbolAddress((void**)&p_qs,   g_qs);
    cudaGetSymbolAddress((void**)&p_kpp,  g_kp_part);
    cudaGetSymbolAddress((void**)&p_tp,   g_T_part);

    __nv_bfloat16 *p_qhi, *p_qlo, *p_khi, *p_klo, *p_ahi, *p_alo;
    __nv_bfloat16 *p_wkhi, *p_wklo, *p_wghi, *p_wglo, *p_wohi, *p_wolo;
    cudaGetSymbolAddress((void**)&p_qhi,  g_qhi);  cudaGetSymbolAddress((void**)&p_qlo,  g_qlo);
    cudaGetSymbolAddress((void**)&p_khi,  g_khi);  cudaGetSymbolAddress((void**)&p_klo,  g_klo);
    cudaGetSymbolAddress((void**)&p_ahi,  g_ahi);  cudaGetSymbolAddress((void**)&p_alo,  g_alo);
    cudaGetSymbolAddress((void**)&p_wkhi, g_wkhi); cudaGetSymbolAddress((void**)&p_wklo, g_wklo);
    cudaGetSymbolAddress((void**)&p_wghi, g_wghi); cudaGetSymbolAddress((void**)&p_wglo, g_wglo);
    cudaGetSymbolAddress((void**)&p_wohi, g_wohi); cudaGetSymbolAddress((void**)&p_wolo, g_wolo);

    cudaFuncSetAttribute(hmma_gemm<0>, cudaFuncAttributeMaxDynamicSharedMemorySize, SMEM_HMMA);
    cudaFuncSetAttribute(hmma_gemm<1>, cudaFuncAttributeMaxDynamicSharedMemorySize, SMEM_HMMA);
    cudaFuncSetAttribute(hmma_gemm<2>, cudaFuncAttributeMaxDynamicSharedMemorySize, SMEM_HMMA);

    build_tables<<<(SEQ * HALF + 255) / 256, 256>>>();

    // fp32 -> bf16 hi/lo splits
    const int nact4 = MTOT * DMODEL / 4;
    const int nw4   = DMODEL * DMODEL / 4;
    split_bf16<<<nact4 / 256, 256>>>(k,  p_khi,  p_klo,  nact4);
    split_bf16<<<nact4 / 256, 256>>>(q,  p_qhi,  p_qlo,  nact4);
    split_bf16<<<nw4 / 256, 256>>>(wk, p_wkhi, p_wklo, nw4);
    split_bf16<<<nw4 / 256, 256>>>(wg, p_wghi, p_wglo, nw4);
    split_bf16<<<nw4 / 256, 256>>>(wo, p_wohi, p_wolo, nw4);

    // keyx = xpos(k @ wk^T) via HMMA
    hmma_gemm<1><<<dim3(8, 128), 256, SMEM_HMMA>>>(p_khi, p_klo, p_wkhi, p_wklo,
                                                   p_keyx, nullptr, nullptr);
    // qs = xpos(q @ wq^T) rows s<64 only (tiny, fp32 SIMT)
    gemm_kernel<1, true><<<dim3(8, 2), 256>>>(q, wq, p_qs);

    // kp / T seq contractions
    seq_reduce<false><<<dim3(16, BATCH, NSEG), 256>>>(p_keyx, wxw, p_kpp);
    seq_reduce<true ><<<dim3(16, BATCH, NSEG), 256>>>(v,      wxw, p_tp);
    finish_kp<<<(BATCH * DMODEL * DKC) / 256, 256>>>(wxb);
    finish_T <<<(BATCH * DKC * DMODEL) / 256, 256>>>();

    vp_kernel<<<dim3(16, BATCH), 256>>>(wv, wxb);
    attn_small<<<dim3(HEADS, BATCH), 64>>>();
    zbar_kernel<<<BATCH, 256>>>(gnw, gnb);
    gn_small<<<BATCH * DKC, 256>>>(gnw, gnb);

    // act = silu((q @ wg^T) * z) -> bf16 split, via HMMA
    hmma_gemm<2><<<dim3(8, 128), 256, SMEM_HMMA>>>(p_qhi, p_qlo, p_wghi, p_wglo,
                                                   nullptr, p_ahi, p_alo);
    // out = act @ wo^T via HMMA
    hmma_gemm<0><<<dim3(8, 128), 256, SMEM_HMMA>>>(p_ahi, p_alo, p_wohi, p_wolo,
                                                   out, nullptr, nullptr);
}

// round 6
// speedup vs baseline: 1.6627x; 1.0063x over previous
#include <cuda_runtime.h>
#include <cuda_bf16.h>
#include <math.h>
#include <stdint.h>

#define BATCH   4
#define SEQ     4096
#define DMODEL  1024
#define HEADS   16
#define DKC     64
#define HALF    512
#define NSEG    4
#define MTOT    (BATCH * SEQ)    /* 16384 */

// ---------------- scratch (device globals; no allocations) ----------------
__device__ float g_cos[SEQ * HALF];
__device__ float g_sin[SEQ * HALF];
__device__ float g_qs[BATCH * DKC * DMODEL];            // xpos(q@wq^T) rows s<64
__device__ float g_qs_part[NSEG * BATCH * DKC * DMODEL];
__device__ float g_kp_part[NSEG * BATCH * DKC * DMODEL];
__device__ float g_T_part [NSEG * BATCH * DKC * DMODEL];
__device__ float g_kp[BATCH * DKC * DMODEL];            // kp[b][e][d]  (e-major!)
__device__ float g_T [BATCH * DKC * DMODEL];            // T[b][e][c]
__device__ float g_vp[BATCH * DMODEL * DKC];            // vp[b][f][e]
__device__ float g_ysmall[BATCH * DKC * DMODEL];
__device__ float g_z[BATCH * DKC * DMODEL];
__device__ float g_zbar[BATCH * DMODEL];

// bf16 split operands
__device__ __nv_bfloat16 g_qhi[MTOT * DMODEL], g_qlo[MTOT * DMODEL];
__device__ __nv_bfloat16 g_khi[MTOT * DMODEL], g_klo[MTOT * DMODEL];
__device__ __nv_bfloat16 g_ahi[MTOT * DMODEL], g_alo[MTOT * DMODEL];   // silu(gate)
__device__ __nv_bfloat16 g_wkhi[DMODEL * DMODEL], g_wklo[DMODEL * DMODEL];
__device__ __nv_bfloat16 g_wghi[DMODEL * DMODEL], g_wglo[DMODEL * DMODEL];
__device__ __nv_bfloat16 g_wohi[DMODEL * DMODEL], g_wolo[DMODEL * DMODEL];
__device__ __nv_bfloat16 g_wxhi[DKC * SEQ],       g_wxlo[DKC * SEQ];
// transposed seq-major operands [b*DMODEL + d][SEQ]
__device__ __nv_bfloat16 g_kxThi[BATCH * DMODEL * SEQ], g_kxTlo[BATCH * DMODEL * SEQ];
__device__ __nv_bfloat16 g_vThi [BATCH * DMODEL * SEQ], g_vTlo [BATCH * DMODEL * SEQ];

// ================= small PTX helpers (plain-sm_103-legal) =================
__device__ __forceinline__ uint32_t smem_u32(const void* p) {
    uint32_t a;
    asm("{ .reg .u64 t; cvta.to.shared.u64 t, %1; cvt.u32.u64 %0, t; }" : "=r"(a) : "l"(p));
    return a;
}
__device__ __forceinline__ void cp16(uint32_t dst, const void* src) {
    asm volatile("cp.async.cg.shared.global [%0], [%1], 16;" :: "r"(dst), "l"(src) : "memory");
}
#define CP_COMMIT() asm volatile("cp.async.commit_group;" ::: "memory")
#define CP_WAIT(N)  asm volatile("cp.async.wait_group %0;" :: "n"(N) : "memory")

__device__ __forceinline__ void ldsm4(uint32_t* r, uint32_t addr) {
    asm volatile("ldmatrix.sync.aligned.m8n8.x4.shared.b16 {%0,%1,%2,%3}, [%4];"
                 : "=r"(r[0]), "=r"(r[1]), "=r"(r[2]), "=r"(r[3]) : "r"(addr));
}
__device__ __forceinline__ void mma16816(float* d, const uint32_t* a, const uint32_t* b) {
    asm volatile("mma.sync.aligned.m16n8k16.row.col.f32.bf16.bf16.f32 "
                 "{%0,%1,%2,%3}, {%4,%5,%6,%7}, {%8,%9}, {%0,%1,%2,%3};"
                 : "+f"(d[0]), "+f"(d[1]), "+f"(d[2]), "+f"(d[3])
                 : "r"(a[0]), "r"(a[1]), "r"(a[2]), "r"(a[3]), "r"(b[0]), "r"(b[1]));
}

// main GEMM SMEM: rows padded to 80B; 3 stages
#define ROWB      80
#define STG_BYTES 40960
#define A_LO_OFF  10240
#define B_HI_OFF  20480
#define B_LO_OFF  30720
#define SMEM_HMMA (3 * STG_BYTES)   /* 122880 */
// epilogue transpose staging pad
#define TP_PAD    136

// seq GEMM SMEM: A 64x32(hi,lo), B 128x32(hi,lo), 3 stages
#define SQ_STG    30720
#define SQ_ALO    5120
#define SQ_B      10240
#define SQ_BLO    10240
#define SMEM_SEQ  (3 * SQ_STG)      /* 92160 */

// ================= xpos tables =================
__global__ void build_tables() {
    int idx = blockIdx.x * blockDim.x + threadIdx.x;
    if (idx >= SEQ * HALF) return;
    int s = idx / HALF, i = idx % HALF;
    float sv    = (2.0f * i + 0.4f * DMODEL) / (1.4f * DMODEL);
    float scale = powf(sv, (float)s / 512.0f);
    float invf  = powf(10000.0f, -(float)i / (float)HALF);
    float ang   = (float)s * invf;
    g_cos[idx] = cosf(ang) * scale;
    g_sin[idx] = sinf(ang) * scale;
}

// ================= fp32 -> (hi, lo) bf16 split =================
__global__ void split_bf16(const float* __restrict__ x, __nv_bfloat16* __restrict__ hi,
                           __nv_bfloat16* __restrict__ lo, int n4) {
    int i = blockIdx.x * blockDim.x + threadIdx.x;
    if (i >= n4) return;
    float4 v = ((const float4*)x)[i];
    __nv_bfloat16 h0 = __float2bfloat16(v.x), h1 = __float2bfloat16(v.y);
    __nv_bfloat16 h2 = __float2bfloat16(v.z), h3 = __float2bfloat16(v.w);
    __nv_bfloat16 l0 = __float2bfloat16(v.x - __bfloat162float(h0));
    __nv_bfloat16 l1 = __float2bfloat16(v.y - __bfloat162float(h1));
    __nv_bfloat16 l2 = __float2bfloat16(v.z - __bfloat162float(h2));
    __nv_bfloat16 l3 = __float2bfloat16(v.w - __bfloat162float(h3));
    __nv_bfloat162* ph = (__nv_bfloat162*)(hi) + i * 2;
    __nv_bfloat162* pl = (__nv_bfloat162*)(lo) + i * 2;
    ph[0] = __halves2bfloat162(h0, h1); ph[1] = __halves2bfloat162(h2, h3);
    pl[0] = __halves2bfloat162(l0, l1); pl[1] = __halves2bfloat162(l2, l3);
}

// ================= v -> vT hi/lo (transpose + split) =================
__global__ __launch_bounds__(256)
void vt_split(const float* __restrict__ v, __nv_bfloat16* __restrict__ th,
              __nv_bfloat16* __restrict__ tl)
{
    __shared__ float ts[64][65];
    const int s0 = blockIdx.x * 64, c0 = blockIdx.y * 64, b = blockIdx.z;
    const int tid = threadIdx.x;
    const int r = tid >> 2, quad = tid & 3;
#pragma unroll
    for (int j = 0; j < 4; ++j) {
        int col = quad * 16 + j * 4;
        float4 x = *(const float4*)(v + ((size_t)b * SEQ + s0 + r) * DMODEL + c0 + col);
        ts[r][col] = x.x; ts[r][col + 1] = x.y; ts[r][col + 2] = x.z; ts[r][col + 3] = x.w;
    }
    __syncthreads();
    uint4 hv[2], lv[2];
    __nv_bfloat16* hh = (__nv_bfloat16*)hv;
    __nv_bfloat16* ll = (__nv_bfloat16*)lv;
#pragma unroll
    for (int j = 0; j < 16; ++j) {
        float x = ts[quad * 16 + j][r];
        hh[j] = __float2bfloat16(x);
        ll[j] = __float2bfloat16(x - __bfloat162float(hh[j]));
    }
    size_t row = ((size_t)b * DMODEL + c0 + r) * SEQ + s0 + quad * 16;
    *(uint4*)(th + row) = hv[0]; *(uint4*)(th + row + 8) = hv[1];
    *(uint4*)(tl + row) = lv[0]; *(uint4*)(tl + row + 8) = lv[1];
}

// ================= HMMA split GEMM: C[m,n] = sum_k A[m,k]*W[n,k] =================
// CTA tile 128x128, warp tile 64x32 (2x4 warps), K = 32 chunks of 32, 3-stage pipeline.
// EPI: 0 fp32 out ; 1 xpos -> keyxT bf16 hi/lo (SMEM-transposed) ; 2 gate*z+silu -> bf16 split.
__device__ __forceinline__ void hmma_load_stage(
    uint32_t sb, int stage, int kc, int m0, int n0, int tid,
    const __nv_bfloat16* __restrict__ Ahi, const __nv_bfloat16* __restrict__ Alo,
    const __nv_bfloat16* __restrict__ Whi, const __nv_bfloat16* __restrict__ Wlo)
{
    const uint32_t base = sb + (uint32_t)stage * STG_BYTES;
    const int koff = kc * 32;
#pragma unroll
    for (int p = 0; p < 2; ++p) {
        int i = p * 256 + tid;
        int r = i >> 2, u = i & 3;
        size_t gofA = (size_t)(m0 + r) * DMODEL + koff + u * 8;
        size_t gofB = (size_t)(n0 + r) * DMODEL + koff + u * 8;
        uint32_t soff = (uint32_t)(r * ROWB + u * 16);
        cp16(base + soff,            Ahi + gofA);
        cp16(base + A_LO_OFF + soff, Alo + gofA);
        cp16(base + B_HI_OFF + soff, Whi + gofB);
        cp16(base + B_LO_OFF + soff, Wlo + gofB);
    }
    CP_COMMIT();
}

template<int EPI>
__global__ __launch_bounds__(256)
void hmma_gemm(const __nv_bfloat16* __restrict__ Ahi, const __nv_bfloat16* __restrict__ Alo,
               const __nv_bfloat16* __restrict__ Whi, const __nv_bfloat16* __restrict__ Wlo,
               float* __restrict__ Cf,
               __nv_bfloat16* __restrict__ Chi, __nv_bfloat16* __restrict__ Clo)
{
    extern __shared__ char smem[];
    const uint32_t sb = smem_u32(smem);
    const int tid = threadIdx.x, wid = tid >> 5, lane = tid & 31;
    const int warp_m = wid >> 2, warp_n = wid & 3;
    const int n0 = blockIdx.x * 128, m0 = blockIdx.y * 128;

    float acc[4][4][4];
#pragma unroll
    for (int i = 0; i < 4; ++i)
#pragma unroll
        for (int j = 0; j < 4; ++j)
#pragma unroll
            for (int c = 0; c < 4; ++c) acc[i][j][c] = 0.f;

    uint32_t aoff[4], boff[2];
#pragma unroll
    for (int atom = 0; atom < 4; ++atom)
        aoff[atom] = (uint32_t)((warp_m * 64 + atom * 16 + (lane & 15)) * ROWB
                                + ((lane >> 4) & 1) * 16);
#pragma unroll
    for (int p = 0; p < 2; ++p)
        boff[p] = (uint32_t)((warp_n * 32 + p * 16 + (lane & 7) + ((lane >> 4) << 3)) * ROWB
                             + ((lane >> 3) & 1) * 16);

    hmma_load_stage(sb, 0, 0, m0, n0, tid, Ahi, Alo, Whi, Wlo);
    hmma_load_stage(sb, 1, 1, m0, n0, tid, Ahi, Alo, Whi, Wlo);
    hmma_load_stage(sb, 2, 2, m0, n0, tid, Ahi, Alo, Whi, Wlo);

    for (int kc = 0; kc < 32; ++kc) {
        if (kc < 30)      { CP_WAIT(2); }
        else if (kc == 30){ CP_WAIT(1); }
        else              { CP_WAIT(0); }
        __syncthreads();
        const uint32_t stgb = sb + (uint32_t)(kc % 3) * STG_BYTES;
#pragma unroll
        for (int ks = 0; ks < 2; ++ks) {
            const uint32_t kb = (uint32_t)(ks * 32);
            uint32_t ahi[4][4], alo[4][4], bhi[2][4], blo[2][4];
#pragma unroll
            for (int atom = 0; atom < 4; ++atom) {
                ldsm4(ahi[atom], stgb + aoff[atom] + kb);
                ldsm4(alo[atom], stgb + A_LO_OFF + aoff[atom] + kb);
            }
#pragma unroll
            for (int p = 0; p < 2; ++p) {
                ldsm4(bhi[p], stgb + B_HI_OFF + boff[p] + kb);
                ldsm4(blo[p], stgb + B_LO_OFF + boff[p] + kb);
            }
#pragma unroll
            for (int im = 0; im < 4; ++im)
#pragma unroll
                for (int in = 0; in < 4; ++in)
                    mma16816(acc[im][in], ahi[im], &bhi[in >> 1][(in & 1) * 2]);
#pragma unroll
            for (int im = 0; im < 4; ++im)
#pragma unroll
                for (int in = 0; in < 4; ++in)
                    mma16816(acc[im][in], alo[im], &bhi[in >> 1][(in & 1) * 2]);
#pragma unroll
            for (int im = 0; im < 4; ++im)
#pragma unroll
                for (int in = 0; in < 4; ++in)
                    mma16816(acc[im][in], ahi[im], &blo[in >> 1][(in & 1) * 2]);
        }
        __syncthreads();
        if (kc + 3 < 32)
            hmma_load_stage(sb, kc % 3, kc + 3, m0, n0, tid, Ahi, Alo, Whi, Wlo);
    }

    // -------- epilogue --------
    if (EPI == 1) {
        // xpos, hi/lo split, stage transposed in SMEM, write keyxT [d][s]
        __nv_bfloat16* sh = (__nv_bfloat16*)smem;
        __nv_bfloat16* sl = sh + 128 * TP_PAD;
#pragma unroll
        for (int im = 0; im < 4; ++im)
#pragma unroll
            for (int in = 0; in < 4; ++in) {
                const int dl = warp_n * 32 + in * 8 + (lane & 3) * 2;
                const int nc = n0 + dl;
#pragma unroll
                for (int half = 0; half < 2; ++half) {
                    const int ml = warp_m * 64 + im * 16 + (lane >> 2) + half * 8;
                    const int s = (m0 + ml) & (SEQ - 1);
                    float v0 = acc[im][in][half * 2 + 0];
                    float v1 = acc[im][in][half * 2 + 1];
                    int p = s * HALF + (nc >> 1);
                    float cs = g_cos[p], sn = g_sin[p];
                    float o0 = v0 * cs - v1 * sn;
                    float o1 = v1 * cs + v0 * sn;
                    __nv_bfloat16 h0 = __float2bfloat16(o0), h1 = __float2bfloat16(o1);
                    __nv_bfloat16 l0 = __float2bfloat16(o0 - __bfloat162float(h0));
                    __nv_bfloat16 l1 = __float2bfloat16(o1 - __bfloat162float(h1));
                    sh[dl * TP_PAD + ml] = h0; sh[(dl + 1) * TP_PAD + ml] = h1;
                    sl[dl * TP_PAD + ml] = l0; sl[(dl + 1) * TP_PAD + ml] = l1;
                }
            }
        __syncthreads();
        const int s0 = m0 & (SEQ - 1), bb = m0 >> 12;
#pragma unroll
        for (int it = 0; it < 8; ++it) {
            int slot = it * 256 + tid;
            int dr = slot >> 4;
            int sc = (slot & 15) * 8;
            size_t grow = ((size_t)(bb * DMODEL + n0 + dr)) * SEQ + s0 + sc;
            *(uint4*)(Chi + grow) = *(uint4*)(sh + dr * TP_PAD + sc);
            *(uint4*)(Clo + grow) = *(uint4*)(sl + dr * TP_PAD + sc);
        }
        return;
    }
#pragma unroll
    for (int im = 0; im < 4; ++im) {
#pragma unroll
        for (int in = 0; in < 4; ++in) {
            const int nc = n0 + warp_n * 32 + in * 8 + (lane & 3) * 2;
#pragma unroll
            for (int half = 0; half < 2; ++half) {
                const int m = m0 + warp_m * 64 + im * 16 + (lane >> 2) + half * 8;
                const int s = m & (SEQ - 1);
                const int bb = m >> 12;
                float v0 = acc[im][in][half * 2 + 0];
                float v1 = acc[im][in][half * 2 + 1];
                if (EPI == 0) {
                    *(float2*)(Cf + (size_t)m * DMODEL + nc) = make_float2(v0, v1);
                } else {
                    const float* zr = (s < DKC) ? (g_z + (bb * DKC + s) * DMODEL)
                                                : (g_zbar + bb * DMODEL);
                    float a0 = v0 * zr[nc];
                    float a1 = v1 * zr[nc + 1];
                    a0 = a0 / (1.f + expf(-a0));
                    a1 = a1 / (1.f + expf(-a1));
                    __nv_bfloat16 h0 = __float2bfloat16(a0), h1 = __float2bfloat16(a1);
                    __nv_bfloat16 l0 = __float2bfloat16(a0 - __bfloat162float(h0));
                    __nv_bfloat16 l1 = __float2bfloat16(a1 - __bfloat162float(h1));
                    *(__nv_bfloat162*)(Chi + (size_t)m * DMODEL + nc) = __halves2bfloat162(h0, h1);
                    *(__nv_bfloat162*)(Clo + (size_t)m * DMODEL + nc) = __halves2bfloat162(l0, l1);
                }
            }
        }
    }
}

// ================= seq HMMA GEMM: C[e,n] = sum_s wx[e,s] * B[n,s] =================
// M=64 (e), N tile 128, K = 1024 per seg (32 chunks of 32). grid (8, BATCH, NSEG).
__device__ __forceinline__ void seq_load_stage(
    uint32_t sb, int stage, int k0, int brow0, int tid,
    const __nv_bfloat16* __restrict__ Ah, const __nv_bfloat16* __restrict__ Al,
    const __nv_bfloat16* __restrict__ Bh, const __nv_bfloat16* __restrict__ Bl)
{
    const uint32_t base = sb + (uint32_t)stage * SQ_STG;
#pragma unroll
    for (int it = 0; it < 2; ++it) {
        int i = it * 256 + tid;
        int hl = i >> 8, r = (i >> 2) & 63, u = i & 3;
        const __nv_bfloat16* src = (hl ? Al : Ah) + (size_t)r * SEQ + k0 + u * 8;
        cp16(base + (uint32_t)(hl * SQ_ALO + r * ROWB + u * 16), src);
    }
#pragma unroll
    for (int it = 0; it < 4; ++it) {
        int i = it * 256 + tid;
        int hl = i >> 9, r = (i >> 2) & 127, u = i & 3;
        const __nv_bfloat16* src = (hl ? Bl : Bh) + (size_t)(brow0 + r) * SEQ + k0 + u * 8;
        cp16(base + (uint32_t)(SQ_B + hl * SQ_BLO + r * ROWB + u * 16), src);
    }
    CP_COMMIT();
}

__global__ __launch_bounds__(256)
void seq_hmma(const __nv_bfloat16* __restrict__ Bh, const __nv_bfloat16* __restrict__ Bl,
              float* __restrict__ part)
{
    extern __shared__ char smem[];
    const uint32_t sb = smem_u32(smem);
    const int tid = threadIdx.x, wid = tid >> 5, lane = tid & 31;
    const int n0 = blockIdx.x * 128, b = blockIdx.y, seg = blockIdx.z;
    const int brow0 = b * DMODEL + n0;
    const int kbase = seg * 1024;

    float acc[4][2][4];
#pragma unroll
    for (int i = 0; i < 4; ++i)
#pragma unroll
        for (int j = 0; j < 2; ++j)
#pragma unroll
            for (int c = 0; c < 4; ++c) acc[i][j][c] = 0.f;

    uint32_t aoff[4];
#pragma unroll
    for (int atom = 0; atom < 4; ++atom)
        aoff[atom] = (uint32_t)((atom * 16 + (lane & 15)) * ROWB + ((lane >> 4) & 1) * 16);
    const uint32_t boff = (uint32_t)((wid * 16 + (lane & 7) + ((lane >> 4) << 3)) * ROWB
                                     + ((lane >> 3) & 1) * 16);

    const __nv_bfloat16* Ah = g_wxhi;
    const __nv_bfloat16* Al = g_wxlo;
    seq_load_stage(sb, 0, kbase + 0,  brow0, tid, Ah, Al, Bh, Bl);
    seq_load_stage(sb, 1, kbase + 32, brow0, tid, Ah, Al, Bh, Bl);
    seq_load_stage(sb, 2, kbase + 64, brow0, tid, Ah, Al, Bh, Bl);

    for (int kc = 0; kc < 32; ++kc) {
        if (kc < 30)      { CP_WAIT(2); }
        else if (kc == 30){ CP_WAIT(1); }
        else              { CP_WAIT(0); }
        __syncthreads();
        const uint32_t stgb = sb + (uint32_t)(kc % 3) * SQ_STG;
#pragma unroll
        for (int ks = 0; ks < 2; ++ks) {
            const uint32_t kb = (uint32_t)(ks * 32);
            uint32_t ahi[4][4], alo[4][4], bhi[4], blo[4];
#pragma unroll
            for (int atom = 0; atom < 4; ++atom) {
                ldsm4(ahi[atom], stgb + aoff[atom] + kb);
                ldsm4(alo[atom], stgb + SQ_ALO + aoff[atom] + kb);
            }
            ldsm4(bhi, stgb + SQ_B + boff + kb);
            ldsm4(blo, stgb + SQ_B + SQ_BLO + boff + kb);
#pragma unroll
            for (int im = 0; im < 4; ++im)
#pragma unroll
                for (int in = 0; in < 2; ++in)
                    mma16816(acc[im][in], ahi[im], &bhi[in * 2]);
#pragma unroll
            for (int im = 0; im < 4; ++im)
#pragma unroll
                for (int in = 0; in < 2; ++in)
                    mma16816(acc[im][in], alo[im], &bhi[in * 2]);
#pragma unroll
            for (int im = 0; im < 4; ++im)
#pragma unroll
                for (int in = 0; in < 2; ++in)
                    mma16816(acc[im][in], ahi[im], &blo[in * 2]);
        }
        __syncthreads();
        if (kc + 3 < 32)
            seq_load_stage(sb, kc % 3, kbase + (kc + 3) * 32, brow0, tid, Ah, Al, Bh, Bl);
    }

    const size_t obase = (size_t)seg * (BATCH * DKC * DMODEL);
#pragma unroll
    for (int im = 0; im < 4; ++im)
#pragma unroll
        for (int in = 0; in < 2; ++in) {
            const int n = n0 + wid * 16 + in * 8 + (lane & 3) * 2;
#pragma unroll
            for (int half = 0; half < 2; ++half) {
                const int e = im * 16 + (lane >> 2) + half * 8;
                *(float2*)(part + obase + ((size_t)(b * DKC + e) << 10) + n) =
                    make_float2(acc[im][in][half * 2], acc[im][in][half * 2 + 1]);
            }
        }
}

__global__ void finish_kp(const float* __restrict__ wxb) {
    int idx = blockIdx.x * blockDim.x + threadIdx.x;   // over BATCH*64*1024 (layout [b][e][d])
    float v = 0.f;
#pragma unroll
    for (int s = 0; s < NSEG; ++s) v += g_kp_part[s * (BATCH * DKC * DMODEL) + idx];
    g_kp[idx] = v + wxb[(idx >> 10) & 63];
}
__global__ void finish_T() {
    int idx = blockIdx.x * blockDim.x + threadIdx.x;
    float v = 0.f;
#pragma unroll
    for (int s = 0; s < NSEG; ++s) v += g_T_part[s * (BATCH * DKC * DMODEL) + idx];
    g_T[idx] = v;
}

// ================= qs: split-K SIMT GEMM (rows s<64 only) =================
__global__ __launch_bounds__(256)
void qs_gemm(const float* __restrict__ q, const float* __restrict__ wq)
{
    __shared__ float As[16][68];
    __shared__ float Bs[16][68];
    const int n0 = blockIdx.x * 64, b = blockIdx.y, seg = blockIdx.z;
    const int tid = threadIdx.x;
    const int ti = tid & 15, te = tid >> 4;
    const int lr = tid >> 2, lc = (tid & 3) * 4;

    float acc[4][4];
#pragma unroll
    for (int i = 0; i < 4; ++i)
#pragma unroll
        for (int j = 0; j < 4; ++j) acc[i][j] = 0.f;

    for (int kt = 0; kt < 16; ++kt) {
        const int k0 = seg * 256 + kt * 16;
        float4 pa = *(const float4*)(q  + ((size_t)b * SEQ + lr) * DMODEL + k0 + lc);
        float4 pb = *(const float4*)(wq + (size_t)(n0 + lr) * DMODEL + k0 + lc);
        As[lc + 0][lr] = pa.x; As[lc + 1][lr] = pa.y; As[lc + 2][lr] = pa.z; As[lc + 3][lr] = pa.w;
        Bs[lc + 0][lr] = pb.x; Bs[lc + 1][lr] = pb.y; Bs[lc + 2][lr] = pb.z; Bs[lc + 3][lr] = pb.w;
        __syncthreads();
#pragma unroll
        for (int kk = 0; kk < 16; ++kk) {
            float a[4], bb[4];
            *(float4*)a  = *(const float4*)&As[kk][te * 4];
            *(float4*)bb = *(const float4*)&Bs[kk][ti * 4];
#pragma unroll
            for (int i = 0; i < 4; ++i)
#pragma unroll
                for (int j = 0; j < 4; ++j)
                    acc[i][j] = fmaf(a[i], bb[j], acc[i][j]);
        }
        __syncthreads();
    }
    const size_t obase = (size_t)seg * (BATCH * DKC * DMODEL);
#pragma unroll
    for (int i = 0; i < 4; ++i)
#pragma unroll
        for (int j = 0; j < 4; ++j)
            g_qs_part[obase + ((size_t)(b * DKC + te * 4 + i) << 10) + n0 + ti * 4 + j] = acc[i][j];
}

__global__ void finish_qs() {
    int idx = blockIdx.x * blockDim.x + threadIdx.x;   // over 256*512 pairs
    int m = idx >> 9, pr = idx & 511;
    float v0 = 0.f, v1 = 0.f;
#pragma unroll
    for (int s = 0; s < NSEG; ++s) {
        const float* p = g_qs_part + (size_t)s * (BATCH * DKC * DMODEL) + ((size_t)m << 10) + pr * 2;
        v0 += p[0]; v1 += p[1];
    }
    int sq = m & 63;
    int p = sq * HALF + pr;
    float cs = g_cos[p], sn = g_sin[p];
    g_qs[((size_t)m << 10) + pr * 2]     = v0 * cs - v1 * sn;
    g_qs[((size_t)m << 10) + pr * 2 + 1] = v1 * cs + v0 * sn;
}

// ================= vp[b,f,e] = sum_c wv[f,c]*T[b,e,c] + wxb[e] =================
__global__ __launch_bounds__(256)
void vp_kernel(const float* __restrict__ wv, const float* __restrict__ wxb)
{
    __shared__ float Wvs[64][68];
    __shared__ float Ts[64][68];
    const int f0 = blockIdx.x * 64;
    const int b  = blockIdx.y;
    const int tid = threadIdx.x;
    const int tf = tid & 15, te = tid >> 4;
    float acc[4][4];
#pragma unroll
    for (int a = 0; a < 4; ++a)
#pragma unroll
        for (int j = 0; j < 4; ++j) acc[a][j] = 0.f;

    for (int ch = 0; ch < 16; ++ch) {
        int cb = ch * 64;
#pragma unroll
        for (int r = 0; r < 16; ++r) {
            int l = r * 256 + tid;
            int row = l >> 6, col = l & 63;
            Wvs[row][col] = wv[(f0 + row) * DMODEL + cb + col];
            Ts[row][col]  = g_T[(b * DKC + row) * DMODEL + cb + col];
        }
        __syncthreads();
        for (int c = 0; c < 64; ++c) {
            float wf0 = Wvs[tf * 4 + 0][c], wf1 = Wvs[tf * 4 + 1][c];
            float wf2 = Wvs[tf * 4 + 2][c], wf3 = Wvs[tf * 4 + 3][c];
            float t0 = Ts[te * 4 + 0][c], t1 = Ts[te * 4 + 1][c];
            float t2 = Ts[te * 4 + 2][c], t3 = Ts[te * 4 + 3][c];
            acc[0][0] += wf0 * t0; acc[0][1] += wf0 * t1; acc[0][2] += wf0 * t2; acc[0][3] += wf0 * t3;
            acc[1][0] += wf1 * t0; acc[1][1] += wf1 * t1; acc[1][2] += wf1 * t2; acc[1][3] += wf1 * t3;
            acc[2][0] += wf2 * t0; acc[2][1] += wf2 * t1; acc[2][2] += wf2 * t2; acc[2][3] += wf2 * t3;
            acc[3][0] += wf3 * t0; acc[3][1] += wf3 * t1; acc[3][2] += wf3 * t2; acc[3][3] += wf3 * t3;
        }
        __syncthreads();
    }
#pragma unroll
    for (int a = 0; a < 4; ++a)
#pragma unroll
        for (int j = 0; j < 4; ++j) {
            int f = f0 + tf * 4 + a, e = te * 4 + j;
            g_vp[(b * DMODEL + f) * DKC + e] = acc[a][j] + wxb[e];
        }
}

// ================= tiny attention (s < 64 rows) =================
__global__ __launch_bounds__(64)
void attn_small()
{
    __shared__ float kps[64][64];   // [d][e]
    __shared__ float vps[64][64];   // [f][e]
    const int h = blockIdx.x, b = blockIdx.y, s = threadIdx.x;
    // kp stored [b][e][d]: thread s loads row d=s for all e (coalesced over s)
#pragma unroll 4
    for (int e = 0; e < 64; ++e)
        kps[s][e] = g_kp[((size_t)(b * DKC + e) << 10) + h * DKC + s];
    for (int l = s; l < 4096; l += 64) {
        int d = l >> 6, e = l & 63;
        vps[d][e] = g_vp[(b * DMODEL + h * DKC + d) * DKC + e];
    }
    __syncthreads();

    float qv[64];
    const float* qp = g_qs + (b * DKC + s) * DMODEL + h * DKC;
#pragma unroll
    for (int d = 0; d < 64; d += 4) {
        float4 t = *(const float4*)(qp + d);
        qv[d] = t.x; qv[d + 1] = t.y; qv[d + 2] = t.z; qv[d + 3] = t.w;
    }
    const float lg0 = logf(1.0f / 32.0f);
    const float lg1 = logf(1.0f / 512.0f);
    const float gamma = 1.0f - expf(lg0 + (lg1 - lg0) * ((float)h / 15.0f));

    float sc[64];
#pragma unroll
    for (int e = 0; e < 64; ++e) {
        float a = 0.f;
#pragma unroll
        for (int d = 0; d < 64; ++d) a = fmaf(qv[d], kps[d][e], a);
        float dt = (e >= s) ? powf(gamma, (float)(e - s)) : 0.0f;
        sc[e] = a * dt;
    }
    float mx = -1e30f;
#pragma unroll
    for (int e = 0; e < 64; ++e) mx = fmaxf(mx, sc[e]);
    float sum = 0.f;
#pragma unroll
    for (int e = 0; e < 64; ++e) { sc[e] = expf(sc[e] - mx); sum += sc[e]; }
    float inv = 1.0f / sum;
#pragma unroll
    for (int f = 0; f < 64; ++f) {
        float a = 0.f;
#pragma unroll
        for (int e = 0; e < 64; ++e) a = fmaf(sc[e], vps[f][e], a);
        g_ysmall[(b * DKC + s) * DMODEL + h * DKC + f] = a * inv;
    }
}

// ================= group norm =================
__device__ __forceinline__ void gn4(float y[4], int d0,
                                    const float* gw, const float* gb, float out[4]) {
    float mu = (y[0] + y[1] + y[2] + y[3]) * 0.25f;
    float var = 0.f;
#pragma unroll
    for (int j = 0; j < 4; ++j) { float dd = y[j] - mu; var += dd * dd; }
    var *= 0.25f;
    float inv = rsqrtf(var + 1e-5f);
#pragma unroll
    for (int j = 0; j < 4; ++j) {
        int d = d0 + j;
        out[j] = (y[j] - mu) * inv * gw[d & 63] + gb[d & 63];
    }
}

__global__ void zbar_kernel(const float* __restrict__ gw, const float* __restrict__ gb) {
    int b = blockIdx.x, t = threadIdx.x;
    int d0 = t * 4;
    float y[4];
#pragma unroll
    for (int j = 0; j < 4; ++j) {
        const float* vp = g_vp + (b * DMODEL + d0 + j) * DKC;
        float s = 0.f;
#pragma unroll
        for (int e = 0; e < 64; ++e) s += vp[e];
        y[j] = s * (1.0f / 64.0f);
    }
    float o[4];
    gn4(y, d0, gw, gb, o);
#pragma unroll
    for (int j = 0; j < 4; ++j) g_zbar[b * DMODEL + d0 + j] = o[j];
}

__global__ void gn_small(const float* __restrict__ gw, const float* __restrict__ gb) {
    int row = blockIdx.x;
    int d0 = threadIdx.x * 4;
    float4 y4 = *(const float4*)(g_ysmall + row * DMODEL + d0);
    float y[4] = { y4.x, y4.y, y4.z, y4.w };
    float o[4];
    gn4(y, d0, gw, gb, o);
    *(float4*)(g_z + row * DMODEL + d0) = make_float4(o[0], o[1], o[2], o[3]);
}

// ================= launch =================
extern "C" void kernel_launch(void* const* d_in, const int* in_sizes, int n_in,
                              void* d_out, int out_size)
{
    const float* q   = (const float*)d_in[0];
    const float* k   = (const float*)d_in[1];
    const float* v   = (const float*)d_in[2];
    const float* wq  = (const float*)d_in[3];
    const float* wk  = (const float*)d_in[4];
    const float* wv  = (const float*)d_in[5];
    const float* wo  = (const float*)d_in[6];
    const float* wg  = (const float*)d_in[7];
    const float* wxw = (const float*)d_in[8];
    const float* wxb = (const float*)d_in[9];
    const float* gnw = (const float*)d_in[10];
    const float* gnb = (const float*)d_in[11];
    float* out = (float*)d_out;

    float *p_kpp, *p_tp;
    cudaGetSymbolAddress((void**)&p_kpp, g_kp_part);
    cudaGetSymbolAddress((void**)&p_tp,  g_T_part);

    __nv_bfloat16 *p_qhi, *p_qlo, *p_khi, *p_klo, *p_ahi, *p_alo;
    __nv_bfloat16 *p_wkhi, *p_wklo, *p_wghi, *p_wglo, *p_wohi, *p_wolo;
    __nv_bfloat16 *p_wxhi, *p_wxlo, *p_kxThi, *p_kxTlo, *p_vThi, *p_vTlo;
    cudaGetSymbolAddress((void**)&p_qhi,  g_qhi);  cudaGetSymbolAddress((void**)&p_qlo,  g_qlo);
    cudaGetSymbolAddress((void**)&p_khi,  g_khi);  cudaGetSymbolAddress((void**)&p_klo,  g_klo);
    cudaGetSymbolAddress((void**)&p_ahi,  g_ahi);  cudaGetSymbolAddress((void**)&p_alo,  g_alo);
    cudaGetSymbolAddress((void**)&p_wkhi, g_wkhi); cudaGetSymbolAddress((void**)&p_wklo, g_wklo);
    cudaGetSymbolAddress((void**)&p_wghi, g_wghi); cudaGetSymbolAddress((void**)&p_wglo, g_wglo);
    cudaGetSymbolAddress((void**)&p_wohi, g_wohi); cudaGetSymbolAddress((void**)&p_wolo, g_wolo);
    cudaGetSymbolAddress((void**)&p_wxhi, g_wxhi); cudaGetSymbolAddress((void**)&p_wxlo, g_wxlo);
    cudaGetSymbolAddress((void**)&p_kxThi, g_kxThi); cudaGetSymbolAddress((void**)&p_kxTlo, g_kxTlo);
    cudaGetSymbolAddress((void**)&p_vThi,  g_vThi);  cudaGetSymbolAddress((void**)&p_vTlo,  g_vTlo);

    cudaFuncSetAttribute(hmma_gemm<0>, cudaFuncAttributeMaxDynamicSharedMemorySize, SMEM_HMMA);
    cudaFuncSetAttribute(hmma_gemm<1>, cudaFuncAttributeMaxDynamicSharedMemorySize, SMEM_HMMA);
    cudaFuncSetAttribute(hmma_gemm<2>, cudaFuncAttributeMaxDynamicSharedMemorySize, SMEM_HMMA);
    cudaFuncSetAttribute(seq_hmma,     cudaFuncAttributeMaxDynamicSharedMemorySize, SMEM_SEQ);

    build_tables<<<(SEQ * HALF + 255) / 256, 256>>>();

    // fp32 -> bf16 hi/lo splits
    const int nact4 = MTOT * DMODEL / 4;
    const int nw4   = DMODEL * DMODEL / 4;
    const int nwx4  = DKC * SEQ / 4;
    split_bf16<<<nact4 / 256, 256>>>(k,   p_khi,  p_klo,  nact4);
    split_bf16<<<nact4 / 256, 256>>>(q,   p_qhi,  p_qlo,  nact4);
    split_bf16<<<nw4 / 256, 256>>>(wk,  p_wkhi, p_wklo, nw4);
    split_bf16<<<nw4 / 256, 256>>>(wg,  p_wghi, p_wglo, nw4);
    split_bf16<<<nw4 / 256, 256>>>(wo,  p_wohi, p_wolo, nw4);
    split_bf16<<<nwx4 / 256, 256>>>(wxw, p_wxhi, p_wxlo, nwx4);

    // v -> vT hi/lo
    vt_split<<<dim3(SEQ / 64, DMODEL / 64, BATCH), 256>>>(v, p_vThi, p_vTlo);

    // keyxT = xpos(k @ wk^T)^T (bf16 hi/lo), via HMMA with transpose epilogue
    hmma_gemm<1><<<dim3(8, 128), 256, SMEM_HMMA>>>(p_khi, p_klo, p_wkhi, p_wklo,
                                                   nullptr, p_kxThi, p_kxTlo);
    // qs = xpos(q @ wq^T) rows s<64 (split-K SIMT)
    qs_gemm<<<dim3(16, BATCH, NSEG), 256>>>(q, wq);
    finish_qs<<<(BATCH * DKC * HALF) / 256, 256>>>();

    // kp[b,e,d] / T[b,e,c] seq contractions via HMMA
    seq_hmma<<<dim3(8, BATCH, NSEG), 256, SMEM_SEQ>>>(p_kxThi, p_kxTlo, p_kpp);
    seq_hmma<<<dim3(8, BATCH, NSEG), 256, SMEM_SEQ>>>(p_vThi,  p_vTlo,  p_tp);
    finish_kp<<<(BATCH * DKC * DMODEL) / 256, 256>>>(wxb);
    finish_T <<<(BATCH * DKC * DMODEL) / 256, 256>>>();

    vp_kernel<<<dim3(16, BATCH), 256>>>(wv, wxb);
    attn_small<<<dim3(HEADS, BATCH), 64>>>();
    zbar_kernel<<<BATCH, 256>>>(gnw, gnb);
    gn_small<<<BATCH * DKC, 256>>>(gnw, gnb);

    // act = silu((q @ wg^T) * z) -> bf16 split, via HMMA
    hmma_gemm<2><<<dim3(8, 128), 256, SMEM_HMMA>>>(p_qhi, p_qlo, p_wghi, p_wglo,
                                                   nullptr, p_ahi, p_alo);
    // out = act @ wo^T via HMMA
    hmma_gemm<0><<<dim3(8, 128), 256, SMEM_HMMA>>>(p_ahi, p_alo, p_wohi, p_wolo,
                                                   out, nullptr, nullptr);
}

// round 7
// speedup vs baseline: 1.9534x; 1.1749x over previous
#include <cuda_runtime.h>
#include <cuda_fp16.h>
#include <math.h>
#include <stdint.h>

#define BATCH   4
#define SEQ     4096
#define DMODEL  1024
#define HEADS   16
#define DKC     64
#define HALF    512
#define NSEG    4
#define MTOT    (BATCH * SEQ)    /* 16384 */

// ---------------- scratch (device globals; no allocations) ----------------
__device__ float g_cos[SEQ * HALF];
__device__ float g_sin[SEQ * HALF];
__device__ float g_qs[BATCH * DKC * DMODEL];
__device__ float g_qs_part[NSEG * BATCH * DKC * DMODEL];
__device__ float g_kp_part[NSEG * BATCH * DKC * DMODEL];
__device__ float g_T_part [NSEG * BATCH * DKC * DMODEL];
__device__ float g_kp[BATCH * DKC * DMODEL];            // kp[b][e][d]
__device__ float g_T [BATCH * DKC * DMODEL];            // T[b][e][c]
__device__ float g_vp[BATCH * DMODEL * DKC];            // vp[b][f][e]
__device__ float g_ysmall[BATCH * DKC * DMODEL];
__device__ float g_z[BATCH * DKC * DMODEL];
__device__ float g_zbar[BATCH * DMODEL];

// fp16 split operands
__device__ __half g_qhi[MTOT * DMODEL], g_qlo[MTOT * DMODEL];
__device__ __half g_khi[MTOT * DMODEL], g_klo[MTOT * DMODEL];
__device__ __half g_ahi[MTOT * DMODEL], g_alo[MTOT * DMODEL];   // silu(gate)
__device__ __half g_wkhi[DMODEL * DMODEL], g_wklo[DMODEL * DMODEL];
__device__ __half g_wghi[DMODEL * DMODEL], g_wglo[DMODEL * DMODEL];
__device__ __half g_wohi[DMODEL * DMODEL], g_wolo[DMODEL * DMODEL];
__device__ __half g_wxhi[DKC * SEQ],       g_wxlo[DKC * SEQ];
// transposed seq-major operands [b*DMODEL + d][SEQ]
__device__ __half g_kxThi[BATCH * DMODEL * SEQ], g_kxTlo[BATCH * DMODEL * SEQ];
__device__ __half g_vThi [BATCH * DMODEL * SEQ], g_vTlo [BATCH * DMODEL * SEQ];

// ================= PTX helpers =================
__device__ __forceinline__ uint32_t smem_u32(const void* p) {
    uint32_t a;
    asm("{ .reg .u64 t; cvta.to.shared.u64 t, %1; cvt.u32.u64 %0, t; }" : "=r"(a) : "l"(p));
    return a;
}
__device__ __forceinline__ void cp16(uint32_t dst, const void* src) {
    asm volatile("cp.async.cg.shared.global [%0], [%1], 16;" :: "r"(dst), "l"(src) : "memory");
}
#define CP_COMMIT() asm volatile("cp.async.commit_group;" ::: "memory")
#define CP_WAIT(N)  asm volatile("cp.async.wait_group %0;" :: "n"(N) : "memory")

__device__ __forceinline__ void ldsm4(uint32_t* r, uint32_t addr) {
    asm volatile("ldmatrix.sync.aligned.m8n8.x4.shared.b16 {%0,%1,%2,%3}, [%4];"
                 : "=r"(r[0]), "=r"(r[1]), "=r"(r[2]), "=r"(r[3]) : "r"(addr));
}
__device__ __forceinline__ void mma16816(float* d, const uint32_t* a, const uint32_t* b) {
    asm volatile("mma.sync.aligned.m16n8k16.row.col.f32.f16.f16.f32 "
                 "{%0,%1,%2,%3}, {%4,%5,%6,%7}, {%8,%9}, {%0,%1,%2,%3};"
                 : "+f"(d[0]), "+f"(d[1]), "+f"(d[2]), "+f"(d[3])
                 : "r"(a[0]), "r"(a[1]), "r"(a[2]), "r"(a[3]), "r"(b[0]), "r"(b[1]));
}
__device__ __forceinline__ __half2 split_pair(float x, float* rest) {
    __half h = __float2half(x);
    *rest = x - __half2float(h);
    return __half2(h, h);   // unused; placeholder
}

// main GEMM SMEM: rows padded to 80B; 3 stages
#define ROWB      80
#define STG_BYTES 40960
#define A_LO_OFF  10240
#define B_HI_OFF  20480
#define B_LO_OFF  30720
#define SMEM_HMMA (3 * STG_BYTES)   /* 122880 */
#define TP_PAD    136

// seq GEMM SMEM
#define SQ_STG    30720
#define SQ_ALO    5120
#define SQ_B      10240
#define SQ_BLO    10240
#define SMEM_SEQ  (3 * SQ_STG)

// ================= xpos tables =================
__global__ void build_tables() {
    int idx = blockIdx.x * blockDim.x + threadIdx.x;
    if (idx >= SEQ * HALF) return;
    int s = idx / HALF, i = idx % HALF;
    float sv    = (2.0f * i + 0.4f * DMODEL) / (1.4f * DMODEL);
    float scale = powf(sv, (float)s / 512.0f);
    float invf  = powf(10000.0f, -(float)i / (float)HALF);
    float ang   = (float)s * invf;
    g_cos[idx] = cosf(ang) * scale;
    g_sin[idx] = sinf(ang) * scale;
}

// ================= fp32 -> (hi, lo) fp16 split =================
__global__ void split_half(const float* __restrict__ x, __half* __restrict__ hi,
                           __half* __restrict__ lo, int n4) {
    int i = blockIdx.x * blockDim.x + threadIdx.x;
    if (i >= n4) return;
    float4 v = ((const float4*)x)[i];
    __half h0 = __float2half(v.x), h1 = __float2half(v.y);
    __half h2 = __float2half(v.z), h3 = __float2half(v.w);
    __half l0 = __float2half(v.x - __half2float(h0));
    __half l1 = __float2half(v.y - __half2float(h1));
    __half l2 = __float2half(v.z - __half2float(h2));
    __half l3 = __float2half(v.w - __half2float(h3));
    __half2* ph = (__half2*)(hi) + i * 2;
    __half2* pl = (__half2*)(lo) + i * 2;
    ph[0] = __half2(h0, h1); ph[1] = __half2(h2, h3);
    pl[0] = __half2(l0, l1); pl[1] = __half2(l2, l3);
}

// ================= v -> vT hi/lo (transpose + split) =================
__global__ __launch_bounds__(256)
void vt_split(const float* __restrict__ v, __half* __restrict__ th,
              __half* __restrict__ tl)
{
    __shared__ float ts[64][65];
    const int s0 = blockIdx.x * 64, c0 = blockIdx.y * 64, b = blockIdx.z;
    const int tid = threadIdx.x;
    const int r = tid >> 2, quad = tid & 3;
#pragma unroll
    for (int j = 0; j < 4; ++j) {
        int col = quad * 16 + j * 4;
        float4 x = *(const float4*)(v + ((size_t)b * SEQ + s0 + r) * DMODEL + c0 + col);
        ts[r][col] = x.x; ts[r][col + 1] = x.y; ts[r][col + 2] = x.z; ts[r][col + 3] = x.w;
    }
    __syncthreads();
    uint4 hv[2], lv[2];
    __half* hh = (__half*)hv;
    __half* ll = (__half*)lv;
#pragma unroll
    for (int j = 0; j < 16; ++j) {
        float x = ts[quad * 16 + j][r];
        hh[j] = __float2half(x);
        ll[j] = __float2half(x - __half2float(hh[j]));
    }
    size_t row = ((size_t)b * DMODEL + c0 + r) * SEQ + s0 + quad * 16;
    *(uint4*)(th + row) = hv[0]; *(uint4*)(th + row + 8) = hv[1];
    *(uint4*)(tl + row) = lv[0]; *(uint4*)(tl + row + 8) = lv[1];
}

// ================= HMMA split GEMM: C[m,n] = sum_k A[m,k]*W[n,k] =================
// CTA 128x128, 16 warps (4x4), warp tile 32x32, K chunks of 32, 3-stage ring,
// single __syncthreads per chunk. PASSES=3: AhWh+AlWh+AhWl ; PASSES=2: AhWh+AlWh.
template<int PASSES>
__device__ __forceinline__ void load_stage512(
    uint32_t sb, int slot, int kc, int m0, int n0, int tid,
    const __half* __restrict__ Ahi, const __half* __restrict__ Alo,
    const __half* __restrict__ Whi, const __half* __restrict__ Wlo)
{
    const uint32_t base = sb + (uint32_t)slot * STG_BYTES;
    const int koff = kc * 32;
    const int NCH = (PASSES == 3) ? 4 : 3;
#pragma unroll
    for (int it = 0; it < NCH; ++it) {
        int i = it * 512 + tid;
        int tile = i >> 9, r = (i >> 2) & 127, u = i & 3;
        const __half* src;
        if      (tile == 0) src = Ahi + (size_t)(m0 + r) * DMODEL + koff + u * 8;
        else if (tile == 1) src = Alo + (size_t)(m0 + r) * DMODEL + koff + u * 8;
        else if (tile == 2) src = Whi + (size_t)(n0 + r) * DMODEL + koff + u * 8;
        else                src = Wlo + (size_t)(n0 + r) * DMODEL + koff + u * 8;
        cp16(base + (uint32_t)(tile * 10240 + r * ROWB + u * 16), src);
    }
    CP_COMMIT();
}

template<int EPI, int PASSES>
__global__ __launch_bounds__(512)
void hmma_gemm(const __half* __restrict__ Ahi, const __half* __restrict__ Alo,
               const __half* __restrict__ Whi, const __half* __restrict__ Wlo,
               float* __restrict__ Cf,
               __half* __restrict__ Chi, __half* __restrict__ Clo)
{
    extern __shared__ char smem[];
    const uint32_t sb = smem_u32(smem);
    const int tid = threadIdx.x, wid = tid >> 5, lane = tid & 31;
    const int warp_m = wid >> 2, warp_n = wid & 3;
    const int n0 = blockIdx.x * 128, m0 = blockIdx.y * 128;

    float acc[2][4][4];
#pragma unroll
    for (int i = 0; i < 2; ++i)
#pragma unroll
        for (int j = 0; j < 4; ++j)
#pragma unroll
            for (int c = 0; c < 4; ++c) acc[i][j][c] = 0.f;

    uint32_t aoff[2], boff[2];
#pragma unroll
    for (int a = 0; a < 2; ++a)
        aoff[a] = (uint32_t)((warp_m * 32 + a * 16 + (lane & 15)) * ROWB
                             + ((lane >> 4) & 1) * 16);
#pragma unroll
    for (int p = 0; p < 2; ++p)
        boff[p] = (uint32_t)((warp_n * 32 + p * 16 + (lane & 7) + ((lane >> 4) << 3)) * ROWB
                             + ((lane >> 3) & 1) * 16);

    load_stage512<PASSES>(sb, 0, 0, m0, n0, tid, Ahi, Alo, Whi, Wlo);
    load_stage512<PASSES>(sb, 1, 1, m0, n0, tid, Ahi, Alo, Whi, Wlo);

    for (int kc = 0; kc < 32; ++kc) {
        if (kc >= 30) { CP_WAIT(0); } else { CP_WAIT(1); }
        __syncthreads();
        if (kc + 2 < 32)
            load_stage512<PASSES>(sb, (kc + 2) % 3, kc + 2, m0, n0, tid, Ahi, Alo, Whi, Wlo);
        const uint32_t stgb = sb + (uint32_t)(kc % 3) * STG_BYTES;
#pragma unroll
        for (int ks = 0; ks < 2; ++ks) {
            const uint32_t kb = (uint32_t)(ks * 32);
            uint32_t ahi[2][4], alo[2][4], bhi[2][4], blo[2][4];
#pragma unroll
            for (int a = 0; a < 2; ++a) {
                ldsm4(ahi[a], stgb + aoff[a] + kb);
                ldsm4(alo[a], stgb + A_LO_OFF + aoff[a] + kb);
            }
#pragma unroll
            for (int p = 0; p < 2; ++p)
                ldsm4(bhi[p], stgb + B_HI_OFF + boff[p] + kb);
            if (PASSES == 3) {
#pragma unroll
                for (int p = 0; p < 2; ++p)
                    ldsm4(blo[p], stgb + B_LO_OFF + boff[p] + kb);
            }
#pragma unroll
            for (int im = 0; im < 2; ++im)
#pragma unroll
                for (int in = 0; in < 4; ++in)
                    mma16816(acc[im][in], ahi[im], &bhi[in >> 1][(in & 1) * 2]);
#pragma unroll
            for (int im = 0; im < 2; ++im)
#pragma unroll
                for (int in = 0; in < 4; ++in)
                    mma16816(acc[im][in], alo[im], &bhi[in >> 1][(in & 1) * 2]);
            if (PASSES == 3) {
#pragma unroll
                for (int im = 0; im < 2; ++im)
#pragma unroll
                    for (int in = 0; in < 4; ++in)
                        mma16816(acc[im][in], ahi[im], &blo[in >> 1][(in & 1) * 2]);
            }
        }
    }

    // -------- epilogue --------
    if (EPI == 1) {
        __syncthreads();   // stage slots reused as transpose buffer
        __half* sh = (__half*)smem;
        __half* sl = sh + 128 * TP_PAD;
#pragma unroll
        for (int im = 0; im < 2; ++im)
#pragma unroll
            for (int in = 0; in < 4; ++in) {
                const int dl = warp_n * 32 + in * 8 + (lane & 3) * 2;
                const int nc = n0 + dl;
#pragma unroll
                for (int half = 0; half < 2; ++half) {
                    const int ml = warp_m * 32 + im * 16 + (lane >> 2) + half * 8;
                    const int s = (m0 + ml) & (SEQ - 1);
                    float v0 = acc[im][in][half * 2 + 0];
                    float v1 = acc[im][in][half * 2 + 1];
                    int p = s * HALF + (nc >> 1);
                    float cs = g_cos[p], sn = g_sin[p];
                    float o0 = v0 * cs - v1 * sn;
                    float o1 = v1 * cs + v0 * sn;
                    __half h0 = __float2half(o0), h1 = __float2half(o1);
                    __half l0 = __float2half(o0 - __half2float(h0));
                    __half l1 = __float2half(o1 - __half2float(h1));
                    sh[dl * TP_PAD + ml] = h0; sh[(dl + 1) * TP_PAD + ml] = h1;
                    sl[dl * TP_PAD + ml] = l0; sl[(dl + 1) * TP_PAD + ml] = l1;
                }
            }
        __syncthreads();
        const int s0 = m0 & (SEQ - 1), bb = m0 >> 12;
#pragma unroll
        for (int it = 0; it < 4; ++it) {
            int slot = it * 512 + tid;
            int dr = slot >> 4;
            int sc = (slot & 15) * 8;
            size_t grow = ((size_t)(bb * DMODEL + n0 + dr)) * SEQ + s0 + sc;
            *(uint4*)(Chi + grow) = *(uint4*)(sh + dr * TP_PAD + sc);
            *(uint4*)(Clo + grow) = *(uint4*)(sl + dr * TP_PAD + sc);
        }
        return;
    }
#pragma unroll
    for (int im = 0; im < 2; ++im) {
#pragma unroll
        for (int in = 0; in < 4; ++in) {
            const int nc = n0 + warp_n * 32 + in * 8 + (lane & 3) * 2;
#pragma unroll
            for (int half = 0; half < 2; ++half) {
                const int m = m0 + warp_m * 32 + im * 16 + (lane >> 2) + half * 8;
                const int s = m & (SEQ - 1);
                const int bb = m >> 12;
                float v0 = acc[im][in][half * 2 + 0];
                float v1 = acc[im][in][half * 2 + 1];
                if (EPI == 0) {
                    *(float2*)(Cf + (size_t)m * DMODEL + nc) = make_float2(v0, v1);
                } else {
                    const float* zr = (s < DKC) ? (g_z + (bb * DKC + s) * DMODEL)
                                                : (g_zbar + bb * DMODEL);
                    float a0 = v0 * zr[nc];
                    float a1 = v1 * zr[nc + 1];
                    a0 = a0 / (1.f + expf(-a0));
                    a1 = a1 / (1.f + expf(-a1));
                    __half h0 = __float2half(a0), h1 = __float2half(a1);
                    __half l0 = __float2half(a0 - __half2float(h0));
                    __half l1 = __float2half(a1 - __half2float(h1));
                    *(__half2*)(Chi + (size_t)m * DMODEL + nc) = __half2(h0, h1);
                    *(__half2*)(Clo + (size_t)m * DMODEL + nc) = __half2(l0, l1);
                }
            }
        }
    }
}

// ================= seq HMMA GEMM: C[e,n] = sum_s wx[e,s] * B[n,s] =================
__device__ __forceinline__ void seq_load_stage(
    uint32_t sb, int stage, int k0, int brow0, int tid,
    const __half* __restrict__ Ah, const __half* __restrict__ Al,
    const __half* __restrict__ Bh, const __half* __restrict__ Bl)
{
    const uint32_t base = sb + (uint32_t)stage * SQ_STG;
#pragma unroll
    for (int it = 0; it < 2; ++it) {
        int i = it * 256 + tid;
        int hl = i >> 8, r = (i >> 2) & 63, u = i & 3;
        const __half* src = (hl ? Al : Ah) + (size_t)r * SEQ + k0 + u * 8;
        cp16(base + (uint32_t)(hl * SQ_ALO + r * ROWB + u * 16), src);
    }
#pragma unroll
    for (int it = 0; it < 4; ++it) {
        int i = it * 256 + tid;
        int hl = i >> 9, r = (i >> 2) & 127, u = i & 3;
        const __half* src = (hl ? Bl : Bh) + (size_t)(brow0 + r) * SEQ + k0 + u * 8;
        cp16(base + (uint32_t)(SQ_B + hl * SQ_BLO + r * ROWB + u * 16), src);
    }
    CP_COMMIT();
}

__global__ __launch_bounds__(256)
void seq_hmma(const __half* __restrict__ Bh, const __half* __restrict__ Bl,
              float* __restrict__ part)
{
    extern __shared__ char smem[];
    const uint32_t sb = smem_u32(smem);
    const int tid = threadIdx.x, wid = tid >> 5, lane = tid & 31;
    const int n0 = blockIdx.x * 128, b = blockIdx.y, seg = blockIdx.z;
    const int brow0 = b * DMODEL + n0;
    const int kbase = seg * 1024;

    float acc[4][2][4];
#pragma unroll
    for (int i = 0; i < 4; ++i)
#pragma unroll
        for (int j = 0; j < 2; ++j)
#pragma unroll
            for (int c = 0; c < 4; ++c) acc[i][j][c] = 0.f;

    uint32_t aoff[4];
#pragma unroll
    for (int atom = 0; atom < 4; ++atom)
        aoff[atom] = (uint32_t)((atom * 16 + (lane & 15)) * ROWB + ((lane >> 4) & 1) * 16);
    const uint32_t boff = (uint32_t)((wid * 16 + (lane & 7) + ((lane >> 4) << 3)) * ROWB
                                     + ((lane >> 3) & 1) * 16);

    const __half* Ah = g_wxhi;
    const __half* Al = g_wxlo;
    seq_load_stage(sb, 0, kbase + 0,  brow0, tid, Ah, Al, Bh, Bl);
    seq_load_stage(sb, 1, kbase + 32, brow0, tid, Ah, Al, Bh, Bl);

    for (int kc = 0; kc < 32; ++kc) {
        if (kc >= 30) { CP_WAIT(0); } else { CP_WAIT(1); }
        __syncthreads();
        if (kc + 2 < 32)
            seq_load_stage(sb, (kc + 2) % 3, kbase + (kc + 2) * 32, brow0, tid, Ah, Al, Bh, Bl);
        const uint32_t stgb = sb + (uint32_t)(kc % 3) * SQ_STG;
#pragma unroll
        for (int ks = 0; ks < 2; ++ks) {
            const uint32_t kb = (uint32_t)(ks * 32);
            uint32_t ahi[4][4], alo[4][4], bhi[4], blo[4];
#pragma unroll
            for (int atom = 0; atom < 4; ++atom) {
                ldsm4(ahi[atom], stgb + aoff[atom] + kb);
                ldsm4(alo[atom], stgb + SQ_ALO + aoff[atom] + kb);
            }
            ldsm4(bhi, stgb + SQ_B + boff + kb);
            ldsm4(blo, stgb + SQ_B + SQ_BLO + boff + kb);
#pragma unroll
            for (int im = 0; im < 4; ++im)
#pragma unroll
                for (int in = 0; in < 2; ++in)
                    mma16816(acc[im][in], ahi[im], &bhi[in * 2]);
#pragma unroll
            for (int im = 0; im < 4; ++im)
#pragma unroll
                for (int in = 0; in < 2; ++in)
                    mma16816(acc[im][in], alo[im], &bhi[in * 2]);
#pragma unroll
            for (int im = 0; im < 4; ++im)
#pragma unroll
                for (int in = 0; in < 2; ++in)
                    mma16816(acc[im][in], ahi[im], &blo[in * 2]);
        }
    }

    const size_t obase = (size_t)seg * (BATCH * DKC * DMODEL);
#pragma unroll
    for (int im = 0; im < 4; ++im)
#pragma unroll
        for (int in = 0; in < 2; ++in) {
            const int n = n0 + wid * 16 + in * 8 + (lane & 3) * 2;
#pragma unroll
            for (int half = 0; half < 2; ++half) {
                const int e = im * 16 + (lane >> 2) + half * 8;
                *(float2*)(part + obase + ((size_t)(b * DKC + e) << 10) + n) =
                    make_float2(acc[im][in][half * 2], acc[im][in][half * 2 + 1]);
            }
        }
}

__global__ void finish_kp(const float* __restrict__ wxb) {
    int idx = blockIdx.x * blockDim.x + threadIdx.x;
    float v = 0.f;
#pragma unroll
    for (int s = 0; s < NSEG; ++s) v += g_kp_part[s * (BATCH * DKC * DMODEL) + idx];
    g_kp[idx] = v + wxb[(idx >> 10) & 63];
}
__global__ void finish_T() {
    int idx = blockIdx.x * blockDim.x + threadIdx.x;
    float v = 0.f;
#pragma unroll
    for (int s = 0; s < NSEG; ++s) v += g_T_part[s * (BATCH * DKC * DMODEL) + idx];
    g_T[idx] = v;
}

// ================= qs: split-K SIMT GEMM (rows s<64 only) =================
__global__ __launch_bounds__(256)
void qs_gemm(const float* __restrict__ q, const float* __restrict__ wq)
{
    __shared__ float As[16][68];
    __shared__ float Bs[16][68];
    const int n0 = blockIdx.x * 64, b = blockIdx.y, seg = blockIdx.z;
    const int tid = threadIdx.x;
    const int ti = tid & 15, te = tid >> 4;
    const int lr = tid >> 2, lc = (tid & 3) * 4;

    float acc[4][4];
#pragma unroll
    for (int i = 0; i < 4; ++i)
#pragma unroll
        for (int j = 0; j < 4; ++j) acc[i][j] = 0.f;

    for (int kt = 0; kt < 16; ++kt) {
        const int k0 = seg * 256 + kt * 16;
        float4 pa = *(const float4*)(q  + ((size_t)b * SEQ + lr) * DMODEL + k0 + lc);
        float4 pb = *(const float4*)(wq + (size_t)(n0 + lr) * DMODEL + k0 + lc);
        As[lc + 0][lr] = pa.x; As[lc + 1][lr] = pa.y; As[lc + 2][lr] = pa.z; As[lc + 3][lr] = pa.w;
        Bs[lc + 0][lr] = pb.x; Bs[lc + 1][lr] = pb.y; Bs[lc + 2][lr] = pb.z; Bs[lc + 3][lr] = pb.w;
        __syncthreads();
#pragma unroll
        for (int kk = 0; kk < 16; ++kk) {
            float a[4], bb[4];
            *(float4*)a  = *(const float4*)&As[kk][te * 4];
            *(float4*)bb = *(const float4*)&Bs[kk][ti * 4];
#pragma unroll
            for (int i = 0; i < 4; ++i)
#pragma unroll
                for (int j = 0; j < 4; ++j)
                    acc[i][j] = fmaf(a[i], bb[j], acc[i][j]);
        }
        __syncthreads();
    }
    const size_t obase = (size_t)seg * (BATCH * DKC * DMODEL);
#pragma unroll
    for (int i = 0; i < 4; ++i)
#pragma unroll
        for (int j = 0; j < 4; ++j)
            g_qs_part[obase + ((size_t)(b * DKC + te * 4 + i) << 10) + n0 + ti * 4 + j] = acc[i][j];
}

__global__ void finish_qs() {
    int idx = blockIdx.x * blockDim.x + threadIdx.x;
    int m = idx >> 9, pr = idx & 511;
    float v0 = 0.f, v1 = 0.f;
#pragma unroll
    for (int s = 0; s < NSEG; ++s) {
        const float* p = g_qs_part + (size_t)s * (BATCH * DKC * DMODEL) + ((size_t)m << 10) + pr * 2;
        v0 += p[0]; v1 += p[1];
    }
    int sq = m & 63;
    int p = sq * HALF + pr;
    float cs = g_cos[p], sn = g_sin[p];
    g_qs[((size_t)m << 10) + pr * 2]     = v0 * cs - v1 * sn;
    g_qs[((size_t)m << 10) + pr * 2 + 1] = v1 * cs + v0 * sn;
}

// ================= vp[b,f,e] = sum_c wv[f,c]*T[b,e,c] + wxb[e] =================
__global__ __launch_bounds__(256)
void vp_kernel(const float* __restrict__ wv, const float* __restrict__ wxb)
{
    __shared__ float Wvs[64][68];
    __shared__ float Ts[64][68];
    const int f0 = blockIdx.x * 64;
    const int b  = blockIdx.y;
    const int tid = threadIdx.x;
    const int tf = tid & 15, te = tid >> 4;
    float acc[4][4];
#pragma unroll
    for (int a = 0; a < 4; ++a)
#pragma unroll
        for (int j = 0; j < 4; ++j) acc[a][j] = 0.f;

    for (int ch = 0; ch < 16; ++ch) {
        int cb = ch * 64;
#pragma unroll
        for (int r = 0; r < 16; ++r) {
            int l = r * 256 + tid;
            int row = l >> 6, col = l & 63;
            Wvs[row][col] = wv[(f0 + row) * DMODEL + cb + col];
            Ts[row][col]  = g_T[(b * DKC + row) * DMODEL + cb + col];
        }
        __syncthreads();
        for (int c = 0; c < 64; ++c) {
            float wf0 = Wvs[tf * 4 + 0][c], wf1 = Wvs[tf * 4 + 1][c];
            float wf2 = Wvs[tf * 4 + 2][c], wf3 = Wvs[tf * 4 + 3][c];
            float t0 = Ts[te * 4 + 0][c], t1 = Ts[te * 4 + 1][c];
            float t2 = Ts[te * 4 + 2][c], t3 = Ts[te * 4 + 3][c];
            acc[0][0] += wf0 * t0; acc[0][1] += wf0 * t1; acc[0][2] += wf0 * t2; acc[0][3] += wf0 * t3;
            acc[1][0] += wf1 * t0; acc[1][1] += wf1 * t1; acc[1][2] += wf1 * t2; acc[1][3] += wf1 * t3;
            acc[2][0] += wf2 * t0; acc[2][1] += wf2 * t1; acc[2][2] += wf2 * t2; acc[2][3] += wf2 * t3;
            acc[3][0] += wf3 * t0; acc[3][1] += wf3 * t1; acc[3][2] += wf3 * t2; acc[3][3] += wf3 * t3;
        }
        __syncthreads();
    }
#pragma unroll
    for (int a = 0; a < 4; ++a)
#pragma unroll
        for (int j = 0; j < 4; ++j) {
            int f = f0 + tf * 4 + a, e = te * 4 + j;
            g_vp[(b * DMODEL + f) * DKC + e] = acc[a][j] + wxb[e];
        }
}

// ================= tiny attention (s < 64 rows) =================
__global__ __launch_bounds__(64)
void attn_small()
{
    __shared__ float kps[64][64];
    __shared__ float vps[64][64];
    const int h = blockIdx.x, b = blockIdx.y, s = threadIdx.x;
#pragma unroll 4
    for (int e = 0; e < 64; ++e)
        kps[s][e] = g_kp[((size_t)(b * DKC + e) << 10) + h * DKC + s];
    for (int l = s; l < 4096; l += 64) {
        int d = l >> 6, e = l & 63;
        vps[d][e] = g_vp[(b * DMODEL + h * DKC + d) * DKC + e];
    }
    __syncthreads();

    float qv[64];
    const float* qp = g_qs + (b * DKC + s) * DMODEL + h * DKC;
#pragma unroll
    for (int d = 0; d < 64; d += 4) {
        float4 t = *(const float4*)(qp + d);
        qv[d] = t.x; qv[d + 1] = t.y; qv[d + 2] = t.z; qv[d + 3] = t.w;
    }
    const float lg0 = logf(1.0f / 32.0f);
    const float lg1 = logf(1.0f / 512.0f);
    const float gamma = 1.0f - expf(lg0 + (lg1 - lg0) * ((float)h / 15.0f));

    float sc[64];
#pragma unroll
    for (int e = 0; e < 64; ++e) {
        float a = 0.f;
#pragma unroll
        for (int d = 0; d < 64; ++d) a = fmaf(qv[d], kps[d][e], a);
        float dt = (e >= s) ? powf(gamma, (float)(e - s)) : 0.0f;
        sc[e] = a * dt;
    }
    float mx = -1e30f;
#pragma unroll
    for (int e = 0; e < 64; ++e) mx = fmaxf(mx, sc[e]);
    float sum = 0.f;
#pragma unroll
    for (int e = 0; e < 64; ++e) { sc[e] = expf(sc[e] - mx); sum += sc[e]; }
    float inv = 1.0f / sum;
#pragma unroll
    for (int f = 0; f < 64; ++f) {
        float a = 0.f;
#pragma unroll
        for (int e = 0; e < 64; ++e) a = fmaf(sc[e], vps[f][e], a);
        g_ysmall[(b * DKC + s) * DMODEL + h * DKC + f] = a * inv;
    }
}

// ================= group norm =================
__device__ __forceinline__ void gn4(float y[4], int d0,
                                    const float* gw, const float* gb, float out[4]) {
    float mu = (y[0] + y[1] + y[2] + y[3]) * 0.25f;
    float var = 0.f;
#pragma unroll
    for (int j = 0; j < 4; ++j) { float dd = y[j] - mu; var += dd * dd; }
    var *= 0.25f;
    float inv = rsqrtf(var + 1e-5f);
#pragma unroll
    for (int j = 0; j < 4; ++j) {
        int d = d0 + j;
        out[j] = (y[j] - mu) * inv * gw[d & 63] + gb[d & 63];
    }
}

__global__ void zbar_kernel(const float* __restrict__ gw, const float* __restrict__ gb) {
    int b = blockIdx.x, t = threadIdx.x;
    int d0 = t * 4;
    float y[4];
#pragma unroll
    for (int j = 0; j < 4; ++j) {
        const float* vp = g_vp + (b * DMODEL + d0 + j) * DKC;
        float s = 0.f;
#pragma unroll
        for (int e = 0; e < 64; ++e) s += vp[e];
        y[j] = s * (1.0f / 64.0f);
    }
    float o[4];
    gn4(y, d0, gw, gb, o);
#pragma unroll
    for (int j = 0; j < 4; ++j) g_zbar[b * DMODEL + d0 + j] = o[j];
}

__global__ void gn_small(const float* __restrict__ gw, const float* __restrict__ gb) {
    int row = blockIdx.x;
    int d0 = threadIdx.x * 4;
    float4 y4 = *(const float4*)(g_ysmall + row * DMODEL + d0);
    float y[4] = { y4.x, y4.y, y4.z, y4.w };
    float o[4];
    gn4(y, d0, gw, gb, o);
    *(float4*)(g_z + row * DMODEL + d0) = make_float4(o[0], o[1], o[2], o[3]);
}

// ================= launch =================
extern "C" void kernel_launch(void* const* d_in, const int* in_sizes, int n_in,
                              void* d_out, int out_size)
{
    const float* q   = (const float*)d_in[0];
    const float* k   = (const float*)d_in[1];
    const float* v   = (const float*)d_in[2];
    const float* wq  = (const float*)d_in[3];
    const float* wk  = (const float*)d_in[4];
    const float* wv  = (const float*)d_in[5];
    const float* wo  = (const float*)d_in[6];
    const float* wg  = (const float*)d_in[7];
    const float* wxw = (const float*)d_in[8];
    const float* wxb = (const float*)d_in[9];
    const float* gnw = (const float*)d_in[10];
    const float* gnb = (const float*)d_in[11];
    float* out = (float*)d_out;

    float *p_kpp, *p_tp;
    cudaGetSymbolAddress((void**)&p_kpp, g_kp_part);
    cudaGetSymbolAddress((void**)&p_tp,  g_T_part);

    __half *p_qhi, *p_qlo, *p_khi, *p_klo, *p_ahi, *p_alo;
    __half *p_wkhi, *p_wklo, *p_wghi, *p_wglo, *p_wohi, *p_wolo;
    __half *p_wxhi, *p_wxlo, *p_kxThi, *p_kxTlo, *p_vThi, *p_vTlo;
    cudaGetSymbolAddress((void**)&p_qhi,  g_qhi);  cudaGetSymbolAddress((void**)&p_qlo,  g_qlo);
    cudaGetSymbolAddress((void**)&p_khi,  g_khi);  cudaGetSymbolAddress((void**)&p_klo,  g_klo);
    cudaGetSymbolAddress((void**)&p_ahi,  g_ahi);  cudaGetSymbolAddress((void**)&p_alo,  g_alo);
    cudaGetSymbolAddress((void**)&p_wkhi, g_wkhi); cudaGetSymbolAddress((void**)&p_wklo, g_wklo);
    cudaGetSymbolAddress((void**)&p_wghi, g_wghi); cudaGetSymbolAddress((void**)&p_wglo, g_wglo);
    cudaGetSymbolAddress((void**)&p_wohi, g_wohi); cudaGetSymbolAddress((void**)&p_wolo, g_wolo);
    cudaGetSymbolAddress((void**)&p_wxhi, g_wxhi); cudaGetSymbolAddress((void**)&p_wxlo, g_wxlo);
    cudaGetSymbolAddress((void**)&p_kxThi, g_kxThi); cudaGetSymbolAddress((void**)&p_kxTlo, g_kxTlo);
    cudaGetSymbolAddress((void**)&p_vThi,  g_vThi);  cudaGetSymbolAddress((void**)&p_vTlo,  g_vTlo);

    cudaFuncSetAttribute((const void*)hmma_gemm<0, 2>, cudaFuncAttributeMaxDynamicSharedMemorySize, SMEM_HMMA);
    cudaFuncSetAttribute((const void*)hmma_gemm<1, 3>, cudaFuncAttributeMaxDynamicSharedMemorySize, SMEM_HMMA);
    cudaFuncSetAttribute((const void*)hmma_gemm<2, 2>, cudaFuncAttributeMaxDynamicSharedMemorySize, SMEM_HMMA);
    cudaFuncSetAttribute((const void*)seq_hmma, cudaFuncAttributeMaxDynamicSharedMemorySize, SMEM_SEQ);

    build_tables<<<(SEQ * HALF + 255) / 256, 256>>>();

    const int nact4 = MTOT * DMODEL / 4;
    const int nw4   = DMODEL * DMODEL / 4;
    const int nwx4  = DKC * SEQ / 4;
    split_half<<<nact4 / 256, 256>>>(k,   p_khi,  p_klo,  nact4);
    split_half<<<nact4 / 256, 256>>>(q,   p_qhi,  p_qlo,  nact4);
    split_half<<<nw4 / 256, 256>>>(wk,  p_wkhi, p_wklo, nw4);
    split_half<<<nw4 / 256, 256>>>(wg,  p_wghi, p_wglo, nw4);
    split_half<<<nw4 / 256, 256>>>(wo,  p_wohi, p_wolo, nw4);
    split_half<<<nwx4 / 256, 256>>>(wxw, p_wxhi, p_wxlo, nwx4);

    vt_split<<<dim3(SEQ / 64, DMODEL / 64, BATCH), 256>>>(v, p_vThi, p_vTlo);

    // keyxT = xpos(k @ wk^T)^T fp16 hi/lo (3-pass)
    hmma_gemm<1, 3><<<dim3(8, 128), 512, SMEM_HMMA>>>(p_khi, p_klo, p_wkhi, p_wklo,
                                                      nullptr, p_kxThi, p_kxTlo);
    // qs = xpos(q @ wq^T) rows s<64
    qs_gemm<<<dim3(16, BATCH, NSEG), 256>>>(q, wq);
    finish_qs<<<(BATCH * DKC * HALF) / 256, 256>>>();

    // kp / T seq contractions via HMMA
    seq_hmma<<<dim3(8, BATCH, NSEG), 256, SMEM_SEQ>>>(p_kxThi, p_kxTlo, p_kpp);
    seq_hmma<<<dim3(8, BATCH, NSEG), 256, SMEM_SEQ>>>(p_vThi,  p_vTlo,  p_tp);
    finish_kp<<<(BATCH * DKC * DMODEL) / 256, 256>>>(wxb);
    finish_T <<<(BATCH * DKC * DMODEL) / 256, 256>>>();

    vp_kernel<<<dim3(16, BATCH), 256>>>(wv, wxb);
    attn_small<<<dim3(HEADS, BATCH), 64>>>();
    zbar_kernel<<<BATCH, 256>>>(gnw, gnb);
    gn_small<<<BATCH * DKC, 256>>>(gnw, gnb);

    // act = silu((q @ wg^T) * z) -> fp16 split (2-pass)
    hmma_gemm<2, 2><<<dim3(8, 128), 512, SMEM_HMMA>>>(p_qhi, p_qlo, p_wghi, p_wglo,
                                                      nullptr, p_ahi, p_alo);
    // out = act @ wo^T (2-pass)
    hmma_gemm<0, 2><<<dim3(8, 128), 512, SMEM_HMMA>>>(p_ahi, p_alo, p_wohi, p_wolo,
                                                      out, nullptr, nullptr);
}